// round 1
// baseline (speedup 1.0000x reference)
#include <cuda_runtime.h>
#include <cuda_bf16.h>
#include <cstdint>

#define Bsz 8
#define Nsq 512
#define DM_ 1024
#define Hh 16
#define DK 64

// ---------------- scratch (static device arrays; no allocation) --------------
__device__ float g_q[Bsz*Hh*Nsq*DK];        // (b,h,n,d)
__device__ float g_k[Bsz*Hh*Nsq*DK];
__device__ float g_v[Bsz*Hh*Nsq*DK];
__device__ float g_logb[(size_t)Bsz*Hh*Nsq*Nsq]; // (b,h,n,m) log(clip(relu(g),1e-6))
__device__ float g_att[Bsz*Nsq*DM_];        // (b,n, h*dv)
__device__ float g_boxf[Bsz*Nsq*8];         // cx,cy,w,h,logw,logh,pad,pad

// ---------------- box feature precompute ------------------------------------
__global__ void boxfeat_kernel(const float* __restrict__ boxes) {
    int i = blockIdx.x * 256 + threadIdx.x;            // < B*N = 4096
    float4 bx = *(const float4*)(boxes + (size_t)i * 4);
    float cx = (bx.x + bx.z) * 0.5f;
    float cy = (bx.y + bx.w) * 0.5f;
    float w  = (bx.z - bx.x) + 1.0f;
    float h  = (bx.w - bx.y) + 1.0f;
    float* o = g_boxf + (size_t)i * 8;
    o[0] = cx; o[1] = cy; o[2] = w; o[3] = h;
    o[4] = __logf(w); o[5] = __logf(h);
}

// ---------------- geometry bias:  logb[b,h,n,m] ------------------------------
__global__ __launch_bounds__(256) void bias_kernel(const float* __restrict__ Wg,
                                                   const float* __restrict__ bg) {
    __shared__ float Wgs[64 * 16];   // [emb_idx][h]
    __shared__ float bgs[16];
    int tid = threadIdx.x;
    for (int i = tid; i < 1024; i += 256) {
        int h = i >> 6, idx = i & 63;
        Wgs[idx * 16 + h] = Wg[i];
    }
    if (tid < 16) bgs[tid] = bg[tid];
    __syncthreads();

    int t = blockIdx.x * 256 + tid;                    // < B*N*N
    int m = t & 511;
    int n = (t >> 9) & 511;
    int b = t >> 18;

    const float* fn = g_boxf + (size_t)(b * 512 + n) * 8;
    const float* fm = g_boxf + (size_t)(b * 512 + m) * 8;
    float cxn = fn[0], cyn = fn[1], wn = fn[2], hn = fn[3], lwn = fn[4], lhn = fn[5];
    float cxm = fm[0], cym = fm[1], lwm = fm[4], lhm = fm[5];

    float pos[4];
    pos[0] = __logf(fmaxf(fabsf(cxn - cxm) / wn, 1e-3f)) * 100.0f;
    pos[1] = __logf(fmaxf(fabsf(cyn - cym) / hn, 1e-3f)) * 100.0f;
    pos[2] = (lwn - lwm) * 100.0f;
    pos[3] = (lhn - lhm) * 100.0f;

    const float DMAT[8] = {1.0f, 0.4216965034f, 0.1778279410f, 0.0749894209f,
                           0.0316227766f, 0.0133352143f, 0.0056234133f, 0.0023713737f};

    float acc[16];
#pragma unroll
    for (int h = 0; h < 16; h++) acc[h] = 0.0f;

#pragma unroll
    for (int d = 0; d < 4; d++) {
#pragma unroll
        for (int j = 0; j < 8; j++) {
            float s, c;
            __sincosf(pos[d] * DMAT[j], &s, &c);
            int idx = d * 8 + j;
            const float* ws = &Wgs[idx * 16];
            const float* wc = &Wgs[(32 + idx) * 16];
#pragma unroll
            for (int h = 0; h < 16; h++)
                acc[h] = fmaf(s, ws[h], fmaf(c, wc[h], acc[h]));
        }
    }

    size_t base = (size_t)(b * 16) * 262144 + (size_t)n * 512 + m;
#pragma unroll
    for (int h = 0; h < 16; h++) {
        float g = acc[h] + bgs[h];
        g = fmaxf(g, 1e-6f);          // relu then clip(1e-6) == fmax(g,1e-6)
        g_logb[base + (size_t)h * 262144] = __logf(g);
    }
}

// ---------------- GEMM:  C = A[M,K] @ W[Nc,K]^T + bias -----------------------
// a_sel: 0 -> use A param, 1 -> use g_att
// mode:  0 -> plain row-major C[M,Nc]; 1 -> scatter to (b,h,s,d) head layout
__global__ __launch_bounds__(256) void gemm_bias_kernel(
        const float* __restrict__ A_p, const float* __restrict__ W,
        const float* __restrict__ bias, float* __restrict__ C_p,
        int a_sel, int c_sel, int mode) {
    const float* A = a_sel ? g_att : A_p;
    float* C = C_p;
    if (c_sel == 1) C = g_q;
    else if (c_sel == 2) C = g_k;
    else if (c_sel == 3) C = g_v;

    __shared__ float As[16 * 132];
    __shared__ float Ws[16 * 132];
    const int K = 1024;
    int tid = threadIdx.x;
    int tx = tid & 15, ty = tid >> 4;
    int m0 = blockIdx.x * 128;
    int n0 = blockIdx.y * 128;

    float acc[8][8];
#pragma unroll
    for (int i = 0; i < 8; i++)
#pragma unroll
        for (int j = 0; j < 8; j++) acc[i][j] = 0.0f;

    int lr0 = tid >> 2;          // 0..63
    int lk0 = (tid & 3) * 4;     // 0,4,8,12

    for (int k0 = 0; k0 < K; k0 += 16) {
#pragma unroll
        for (int p = 0; p < 2; p++) {
            int row = lr0 + p * 64;
            float4 va = *(const float4*)(A + (size_t)(m0 + row) * K + k0 + lk0);
            As[(lk0 + 0) * 132 + row] = va.x;
            As[(lk0 + 1) * 132 + row] = va.y;
            As[(lk0 + 2) * 132 + row] = va.z;
            As[(lk0 + 3) * 132 + row] = va.w;
            float4 vw = *(const float4*)(W + (size_t)(n0 + row) * K + k0 + lk0);
            Ws[(lk0 + 0) * 132 + row] = vw.x;
            Ws[(lk0 + 1) * 132 + row] = vw.y;
            Ws[(lk0 + 2) * 132 + row] = vw.z;
            Ws[(lk0 + 3) * 132 + row] = vw.w;
        }
        __syncthreads();
#pragma unroll
        for (int kk = 0; kk < 16; kk++) {
            float a[8], b[8];
            *(float4*)&a[0] = *(const float4*)&As[kk * 132 + ty * 8];
            *(float4*)&a[4] = *(const float4*)&As[kk * 132 + ty * 8 + 4];
            *(float4*)&b[0] = *(const float4*)&Ws[kk * 132 + tx * 8];
            *(float4*)&b[4] = *(const float4*)&Ws[kk * 132 + tx * 8 + 4];
#pragma unroll
            for (int i = 0; i < 8; i++)
#pragma unroll
                for (int j = 0; j < 8; j++)
                    acc[i][j] = fmaf(a[i], b[j], acc[i][j]);
        }
        __syncthreads();
    }

#pragma unroll
    for (int i = 0; i < 8; i++) {
        int r = m0 + ty * 8 + i;
#pragma unroll
        for (int jv = 0; jv < 2; jv++) {
            int c = n0 + tx * 8 + jv * 4;
            float4 o;
            o.x = acc[i][jv * 4 + 0] + bias[c + 0];
            o.y = acc[i][jv * 4 + 1] + bias[c + 1];
            o.z = acc[i][jv * 4 + 2] + bias[c + 2];
            o.w = acc[i][jv * 4 + 3] + bias[c + 3];
            if (mode == 1) {
                int b = r >> 9, s = r & 511;
                int h = c >> 6, d = c & 63;
                *(float4*)&C[((size_t)((b * 16 + h) * 512 + s)) * 64 + d] = o;
            } else {
                *(float4*)&C[(size_t)r * 1024 + c] = o;
            }
        }
    }
}

// ---------------- flash attention with geometry bias -------------------------
__global__ __launch_bounds__(256) void attn_kernel() {
    __shared__ float Qs[64 * 64];   // [row][d]
    __shared__ float KPs[64 * 64];  // K^T [d][col], then reused as P [row][col]
    __shared__ float Vs[64 * 64];   // [col][dv]

    int tid = threadIdx.x;
    int tx = tid & 15, ty = tid >> 4;
    int q0 = blockIdx.x * 64;
    int bh = blockIdx.y;            // 0..127
    const float* qp  = g_q + (size_t)bh * 512 * 64;
    const float* kp  = g_k + (size_t)bh * 512 * 64;
    const float* vp  = g_v + (size_t)bh * 512 * 64;
    const float* lbp = g_logb + (size_t)bh * 512 * 512;

#pragma unroll
    for (int p = 0; p < 4; p++) {
        int id = tid + p * 256;
        int row = id >> 4, d4 = (id & 15) * 4;
        *(float4*)&Qs[row * 64 + d4] = *(const float4*)&qp[(size_t)(q0 + row) * 64 + d4];
    }

    float m_i[4], l_i[4], o[4][4];
#pragma unroll
    for (int i = 0; i < 4; i++) {
        m_i[i] = -1e30f; l_i[i] = 0.0f;
#pragma unroll
        for (int j = 0; j < 4; j++) o[i][j] = 0.0f;
    }

    for (int k0 = 0; k0 < 512; k0 += 64) {
        // K^T (transpose on store; col==lane -> conflict-free), V natural
#pragma unroll
        for (int p = 0; p < 4; p++) {
            int id = tid + p * 256;
            int colK = id & 63, d4K = (id >> 6) * 4;
            float4 kv = *(const float4*)&kp[(size_t)(k0 + colK) * 64 + d4K];
            KPs[(d4K + 0) * 64 + colK] = kv.x;
            KPs[(d4K + 1) * 64 + colK] = kv.y;
            KPs[(d4K + 2) * 64 + colK] = kv.z;
            KPs[(d4K + 3) * 64 + colK] = kv.w;
            int rowV = id >> 4, d4V = (id & 15) * 4;
            *(float4*)&Vs[rowV * 64 + d4V] = *(const float4*)&vp[(size_t)(k0 + rowV) * 64 + d4V];
        }
        __syncthreads();

        // S = Q K^T
        float s[4][4];
#pragma unroll
        for (int i = 0; i < 4; i++)
#pragma unroll
            for (int j = 0; j < 4; j++) s[i][j] = 0.0f;
#pragma unroll 8
        for (int d = 0; d < 64; d++) {
            float4 bb = *(const float4*)&KPs[d * 64 + tx * 4];
#pragma unroll
            for (int i = 0; i < 4; i++) {
                float a = Qs[(ty * 4 + i) * 64 + d];
                s[i][0] = fmaf(a, bb.x, s[i][0]);
                s[i][1] = fmaf(a, bb.y, s[i][1]);
                s[i][2] = fmaf(a, bb.z, s[i][2]);
                s[i][3] = fmaf(a, bb.w, s[i][3]);
            }
        }
        // scale + geometry bias
#pragma unroll
        for (int i = 0; i < 4; i++) {
            float4 lb = *(const float4*)&lbp[(size_t)(q0 + ty * 4 + i) * 512 + k0 + tx * 4];
            s[i][0] = s[i][0] * 0.125f + lb.x;
            s[i][1] = s[i][1] * 0.125f + lb.y;
            s[i][2] = s[i][2] * 0.125f + lb.z;
            s[i][3] = s[i][3] * 0.125f + lb.w;
        }
        // online softmax (row groups = 16 lanes sharing ty)
#pragma unroll
        for (int i = 0; i < 4; i++) {
            float rm = fmaxf(fmaxf(s[i][0], s[i][1]), fmaxf(s[i][2], s[i][3]));
#pragma unroll
            for (int off = 8; off; off >>= 1)
                rm = fmaxf(rm, __shfl_xor_sync(0xffffffffu, rm, off, 16));
            float mn = fmaxf(m_i[i], rm);
            float corr = __expf(m_i[i] - mn);
            m_i[i] = mn;
            float ps = 0.0f;
#pragma unroll
            for (int j = 0; j < 4; j++) { s[i][j] = __expf(s[i][j] - mn); ps += s[i][j]; }
#pragma unroll
            for (int off = 8; off; off >>= 1)
                ps += __shfl_xor_sync(0xffffffffu, ps, off, 16);
            l_i[i] = l_i[i] * corr + ps;
#pragma unroll
            for (int j = 0; j < 4; j++) o[i][j] *= corr;
        }
        __syncthreads();      // everyone done reading K^T
#pragma unroll
        for (int i = 0; i < 4; i++)
            *(float4*)&KPs[(ty * 4 + i) * 64 + tx * 4] =
                make_float4(s[i][0], s[i][1], s[i][2], s[i][3]);
        __syncthreads();
        // O += P V
#pragma unroll 8
        for (int c = 0; c < 64; c++) {
            float4 vv = *(const float4*)&Vs[c * 64 + tx * 4];
#pragma unroll
            for (int i = 0; i < 4; i++) {
                float a = KPs[(ty * 4 + i) * 64 + c];
                o[i][0] = fmaf(a, vv.x, o[i][0]);
                o[i][1] = fmaf(a, vv.y, o[i][1]);
                o[i][2] = fmaf(a, vv.z, o[i][2]);
                o[i][3] = fmaf(a, vv.w, o[i][3]);
            }
        }
        __syncthreads();
    }

    int b = bh >> 4, h = bh & 15;
#pragma unroll
    for (int i = 0; i < 4; i++) {
        float inv = 1.0f / l_i[i];
        float4 ov = make_float4(o[i][0] * inv, o[i][1] * inv, o[i][2] * inv, o[i][3] * inv);
        *(float4*)&g_att[(size_t)(b * 512 + q0 + ty * 4 + i) * 1024 + h * 64 + tx * 4] = ov;
    }
}

// ---------------- launch ------------------------------------------------------
extern "C" void kernel_launch(void* const* d_in, const int* in_sizes, int n_in,
                              void* d_out, int out_size) {
    (void)in_sizes; (void)n_in; (void)out_size;
    const float* queries = (const float*)d_in[0];
    const float* keys    = (const float*)d_in[1];
    const float* values  = (const float*)d_in[2];
    const float* boxes   = (const float*)d_in[3];
    const float* Wq = (const float*)d_in[4];
    const float* bq = (const float*)d_in[5];
    const float* Wk = (const float*)d_in[6];
    const float* bk = (const float*)d_in[7];
    const float* Wv = (const float*)d_in[8];
    const float* bv = (const float*)d_in[9];
    const float* Wo = (const float*)d_in[10];
    const float* bo = (const float*)d_in[11];
    const float* Wg = (const float*)d_in[12];
    const float* bg = (const float*)d_in[13];
    float* out = (float*)d_out;

    boxfeat_kernel<<<16, 256>>>(boxes);
    bias_kernel<<<8192, 256>>>(Wg, bg);
    gemm_bias_kernel<<<dim3(32, 8), 256>>>(queries, Wq, bq, nullptr, 0, 1, 1);
    gemm_bias_kernel<<<dim3(32, 8), 256>>>(keys,    Wk, bk, nullptr, 0, 2, 1);
    gemm_bias_kernel<<<dim3(32, 8), 256>>>(values,  Wv, bv, nullptr, 0, 3, 1);
    attn_kernel<<<dim3(8, 128), 256>>>();
    gemm_bias_kernel<<<dim3(32, 8), 256>>>(nullptr, Wo, bo, out, 1, 0, 0);
}

// round 4
// speedup vs baseline: 1.6832x; 1.6832x over previous
#include <cuda_runtime.h>
#include <cuda_bf16.h>
#include <cstdint>

#define Bsz 8
#define Nsq 512
#define DM_ 1024
#define Hh 16
#define DK 64

// ---------------- scratch (static device arrays; no allocation) --------------
__device__ float g_q[Bsz*Hh*Nsq*DK];        // (b,h,n,d)
__device__ float g_k[Bsz*Hh*Nsq*DK];
__device__ float g_v[Bsz*Hh*Nsq*DK];
__device__ float g_logb[(size_t)Bsz*Hh*Nsq*Nsq]; // (b,h,n,m)
__device__ float g_att[Bsz*Nsq*DM_];        // (b,n, h*dv)
__device__ float g_boxf[Bsz*Nsq*8];         // cx,cy,w,h,logw,logh

// ---------------- helpers ----------------------------------------------------
__device__ __forceinline__ uint32_t smem_u32(const void* p) {
    uint32_t a;
    asm("{ .reg .u64 t; cvta.to.shared.u64 t, %1; cvt.u32.u64 %0, t; }" : "=r"(a) : "l"(p));
    return a;
}

#define LDSM4(r, a) \
    asm volatile("ldmatrix.sync.aligned.m8n8.x4.shared.b16 {%0,%1,%2,%3}, [%4];" \
        : "=r"((r)[0]), "=r"((r)[1]), "=r"((r)[2]), "=r"((r)[3]) : "r"(a))

__device__ __forceinline__ void mma16816(float* c, const uint32_t* a, const uint32_t* b) {
    asm volatile("mma.sync.aligned.m16n8k16.row.col.f32.bf16.bf16.f32 "
        "{%0,%1,%2,%3}, {%4,%5,%6,%7}, {%8,%9}, {%0,%1,%2,%3};"
        : "+f"(c[0]), "+f"(c[1]), "+f"(c[2]), "+f"(c[3])
        : "r"(a[0]), "r"(a[1]), "r"(a[2]), "r"(a[3]), "r"(b[0]), "r"(b[1]));
}

// split two floats into packed bf16x2 hi + bf16x2 lo (residual)
__device__ __forceinline__ void split2(float x, float y, uint32_t& hi, uint32_t& lo) {
    asm("cvt.rn.bf16x2.f32 %0, %1, %2;" : "=r"(hi) : "f"(y), "f"(x));
    float fx = __uint_as_float(hi << 16);
    float fy = __uint_as_float(hi & 0xffff0000u);
    asm("cvt.rn.bf16x2.f32 %0, %1, %2;" : "=r"(lo) : "f"(y - fy), "f"(x - fx));
}

// ---------------- box feature precompute ------------------------------------
__global__ void boxfeat_kernel(const float* __restrict__ boxes) {
    int i = blockIdx.x * 256 + threadIdx.x;            // < B*N = 4096
    float4 bx = *(const float4*)(boxes + (size_t)i * 4);
    float cx = (bx.x + bx.z) * 0.5f;
    float cy = (bx.y + bx.w) * 0.5f;
    float w  = (bx.z - bx.x) + 1.0f;
    float h  = (bx.w - bx.y) + 1.0f;
    float* o = g_boxf + (size_t)i * 8;
    o[0] = cx; o[1] = cy; o[2] = w; o[3] = h;
    o[4] = __logf(w); o[5] = __logf(h);
}

// ---------------- geometry bias:  logb[b,h,n,m] ------------------------------
__global__ __launch_bounds__(256) void bias_kernel(const float* __restrict__ Wg,
                                                   const float* __restrict__ bg) {
    __shared__ float Wgs[64 * 16];   // [emb_idx][h]
    __shared__ float bgs[16];
    int tid = threadIdx.x;
    for (int i = tid; i < 1024; i += 256) {
        int h = i >> 6, idx = i & 63;
        Wgs[idx * 16 + h] = Wg[i];
    }
    if (tid < 16) bgs[tid] = bg[tid];
    __syncthreads();

    int t = blockIdx.x * 256 + tid;                    // < B*N*N
    int m = t & 511;
    int n = (t >> 9) & 511;
    int b = t >> 18;

    const float* fn = g_boxf + (size_t)(b * 512 + n) * 8;
    const float* fm = g_boxf + (size_t)(b * 512 + m) * 8;
    float cxn = fn[0], cyn = fn[1], wn = fn[2], hn = fn[3], lwn = fn[4], lhn = fn[5];
    float cxm = fm[0], cym = fm[1], lwm = fm[4], lhm = fm[5];

    float pos[4];
    pos[0] = __logf(fmaxf(fabsf(cxn - cxm) / wn, 1e-3f)) * 100.0f;
    pos[1] = __logf(fmaxf(fabsf(cyn - cym) / hn, 1e-3f)) * 100.0f;
    pos[2] = (lwn - lwm) * 100.0f;
    pos[3] = (lhn - lhm) * 100.0f;

    const float DMAT[8] = {1.0f, 0.4216965034f, 0.1778279410f, 0.0749894209f,
                           0.0316227766f, 0.0133352143f, 0.0056234133f, 0.0023713737f};

    float acc[16];
#pragma unroll
    for (int h = 0; h < 16; h++) acc[h] = 0.0f;

#pragma unroll
    for (int d = 0; d < 4; d++) {
#pragma unroll
        for (int j = 0; j < 8; j++) {
            float s, c;
            __sincosf(pos[d] * DMAT[j], &s, &c);
            int idx = d * 8 + j;
            const float* ws = &Wgs[idx * 16];
            const float* wc = &Wgs[(32 + idx) * 16];
#pragma unroll
            for (int h = 0; h < 16; h++)
                acc[h] = fmaf(s, ws[h], fmaf(c, wc[h], acc[h]));
        }
    }

    size_t base = (size_t)(b * 16) * 262144 + (size_t)n * 512 + m;
#pragma unroll
    for (int h = 0; h < 16; h++) {
        float g = acc[h] + bgs[h];
        g = fmaxf(g, 1e-6f);
        g_logb[base + (size_t)h * 262144] = __logf(g);
    }
}

// ============ mma.sync GEMM: C[M,1024] = A[M,1024] @ W[1024,1024]^T + bias ====
// bf16x3 split for fp32-grade accuracy. 128x128 CTA tile, 8 warps of 32x64.
// Smem per stage: Ah,Al,Bh,Bl each 128 rows x 80B (32 bf16 + 8 pad) = 10240 B.
static constexpr int STAGE_B = 4 * 128 * 80;          // 40960
static constexpr int MG_SMEM = 2 * STAGE_B;           // 81920

__global__ __launch_bounds__(256) void mma_gemm_kernel(
        const float* __restrict__ A0, const float* __restrict__ W0,
        const float* __restrict__ b0p, float* __restrict__ C0,
        const float* __restrict__ A1, const float* __restrict__ W1,
        const float* __restrict__ b1p,
        const float* __restrict__ A2, const float* __restrict__ W2,
        const float* __restrict__ b2p,
        int a_sel, int c_sel_base, int mode) {
    extern __shared__ char smem[];
    int z = blockIdx.z;
    const float* A;
    if (a_sel == 1) A = g_att;
    else A = (z == 0) ? A0 : (z == 1) ? A1 : A2;
    const float* W = (z == 0) ? W0 : (z == 1) ? W1 : W2;
    const float* bias = (z == 0) ? b0p : (z == 1) ? b1p : b2p;
    float* C;
    if (c_sel_base == 0) C = C0;
    else C = (z == 0) ? g_q : (z == 1) ? g_k : g_v;

    uint32_t sbase = smem_u32(smem);
    int tid = threadIdx.x;
    int lane = tid & 31, wid = tid >> 5;
    int wm = wid & 3, wn = wid >> 2;           // warp tile: rows wm*32, cols wn*64
    int m0 = blockIdx.x * 128, n0 = blockIdx.y * 128;

    // per-thread gmem load coords: idx = tid + p*256 -> row idx>>3, float4 idx&7
    int gr = tid >> 3, gq = tid & 7;           // gr 0..31 (+32*p), gq 0..7

    // ldmatrix base offsets (bytes within one 128x80B matrix)
    uint32_t aOff = (uint32_t)(wm * 32 + (lane & 15)) * 80 + (uint32_t)(lane >> 4) * 16;
    uint32_t bOff = (uint32_t)(wn * 64 + (lane & 7) + ((lane >> 4) & 1) * 8) * 80
                  + (uint32_t)((lane >> 3) & 1) * 16;

    float acc[2][8][4];
#pragma unroll
    for (int i = 0; i < 2; i++)
#pragma unroll
        for (int j = 0; j < 8; j++)
#pragma unroll
            for (int q = 0; q < 4; q++) acc[i][j][q] = 0.0f;

    float4 stA[4], stB[4];

    // ---- load chunk 0 ----
#pragma unroll
    for (int p = 0; p < 4; p++) {
        int r = gr + p * 32;
        stA[p] = *(const float4*)(A + (size_t)(m0 + r) * 1024 + gq * 4);
        stB[p] = *(const float4*)(W + (size_t)(n0 + r) * 1024 + gq * 4);
    }

    for (int c = 0; c < 32; ++c) {
        int stage = c & 1;
        // store staged chunk into smem buffers (stage)
        {
            char* sb = smem + stage * STAGE_B;
#pragma unroll
            for (int p = 0; p < 4; p++) {
                int r = gr + p * 32;
                uint32_t off = (uint32_t)r * 80 + (uint32_t)gq * 8;
                uint32_t h0, l0, h1, l1;
                split2(stA[p].x, stA[p].y, h0, l0);
                split2(stA[p].z, stA[p].w, h1, l1);
                *(uint2*)(sb + off)         = make_uint2(h0, h1);
                *(uint2*)(sb + 10240 + off) = make_uint2(l0, l1);
                split2(stB[p].x, stB[p].y, h0, l0);
                split2(stB[p].z, stB[p].w, h1, l1);
                *(uint2*)(sb + 20480 + off) = make_uint2(h0, h1);
                *(uint2*)(sb + 30720 + off) = make_uint2(l0, l1);
            }
        }
        __syncthreads();

        // prefetch next chunk's gmem while computing
        if (c + 1 < 32) {
            int k0 = (c + 1) * 32;
#pragma unroll
            for (int p = 0; p < 4; p++) {
                int r = gr + p * 32;
                stA[p] = *(const float4*)(A + (size_t)(m0 + r) * 1024 + k0 + gq * 4);
                stB[p] = *(const float4*)(W + (size_t)(n0 + r) * 1024 + k0 + gq * 4);
            }
        }

        // ---- compute on buffers (stage) ----
        uint32_t base = sbase + stage * STAGE_B;
#pragma unroll
        for (int k16 = 0; k16 < 2; k16++) {
            uint32_t ah[2][4], al[2][4];
#pragma unroll
            for (int mt = 0; mt < 2; mt++) {
                uint32_t ao = base + aOff + (uint32_t)mt * (16 * 80) + (uint32_t)k16 * 32;
                LDSM4(ah[mt], ao);
                LDSM4(al[mt], ao + 10240);
            }
#pragma unroll
            for (int ntp = 0; ntp < 4; ntp++) {
                uint32_t bh[4], bl[4];
                uint32_t bo = base + 20480 + bOff + (uint32_t)ntp * (16 * 80) + (uint32_t)k16 * 32;
                LDSM4(bh, bo);
                LDSM4(bl, bo + 10240);
#pragma unroll
                for (int mt = 0; mt < 2; mt++) {
#pragma unroll
                    for (int h8 = 0; h8 < 2; h8++) {
                        float* cc = acc[mt][ntp * 2 + h8];
                        mma16816(cc, ah[mt], bh + h8 * 2);  // hi*hi
                        mma16816(cc, ah[mt], bl + h8 * 2);  // hi*lo
                        mma16816(cc, al[mt], bh + h8 * 2);  // lo*hi
                    }
                }
            }
        }
        __syncthreads();
    }

    // ---- epilogue ----
#pragma unroll
    for (int mt = 0; mt < 2; mt++) {
#pragma unroll
        for (int nt8 = 0; nt8 < 8; nt8++) {
            const float* cc = acc[mt][nt8];
            int row = m0 + wm * 32 + mt * 16 + (lane >> 2);
            int col = n0 + wn * 64 + nt8 * 8 + (lane & 3) * 2;
            float bx = bias[col], by = bias[col + 1];
            float2 v0 = make_float2(cc[0] + bx, cc[1] + by);
            float2 v1 = make_float2(cc[2] + bx, cc[3] + by);
            if (mode == 1) {
                int bb = row >> 9, s = row & 511;
                int h = col >> 6, d = col & 63;
                size_t p0 = ((size_t)((bb * 16 + h) * 512 + s)) * 64 + d;
                *(float2*)&C[p0] = v0;
                int bb2 = (row + 8) >> 9, s2 = (row + 8) & 511;
                size_t p1 = ((size_t)((bb2 * 16 + h) * 512 + s2)) * 64 + d;
                *(float2*)&C[p1] = v1;
            } else {
                *(float2*)&C[(size_t)row * 1024 + col] = v0;
                *(float2*)&C[(size_t)(row + 8) * 1024 + col] = v1;
            }
        }
    }
}

// ---------------- flash attention with geometry bias -------------------------
__global__ __launch_bounds__(256) void attn_kernel() {
    __shared__ float Qs[64 * 64];   // [row][d]
    __shared__ float KPs[64 * 64];  // K^T [d][col], then reused as P [row][col]
    __shared__ float Vs[64 * 64];   // [col][dv]

    int tid = threadIdx.x;
    int tx = tid & 15, ty = tid >> 4;
    int q0 = blockIdx.x * 64;
    int bh = blockIdx.y;            // 0..127
    const float* qp  = g_q + (size_t)bh * 512 * 64;
    const float* kp  = g_k + (size_t)bh * 512 * 64;
    const float* vp  = g_v + (size_t)bh * 512 * 64;
    const float* lbp = g_logb + (size_t)bh * 512 * 512;

#pragma unroll
    for (int p = 0; p < 4; p++) {
        int id = tid + p * 256;
        int row = id >> 4, d4 = (id & 15) * 4;
        *(float4*)&Qs[row * 64 + d4] = *(const float4*)&qp[(size_t)(q0 + row) * 64 + d4];
    }

    float m_i[4], l_i[4], o[4][4];
#pragma unroll
    for (int i = 0; i < 4; i++) {
        m_i[i] = -1e30f; l_i[i] = 0.0f;
#pragma unroll
        for (int j = 0; j < 4; j++) o[i][j] = 0.0f;
    }

    for (int k0 = 0; k0 < 512; k0 += 64) {
#pragma unroll
        for (int p = 0; p < 4; p++) {
            int id = tid + p * 256;
            int colK = id & 63, d4K = (id >> 6) * 4;
            float4 kv = *(const float4*)&kp[(size_t)(k0 + colK) * 64 + d4K];
            KPs[(d4K + 0) * 64 + colK] = kv.x;
            KPs[(d4K + 1) * 64 + colK] = kv.y;
            KPs[(d4K + 2) * 64 + colK] = kv.z;
            KPs[(d4K + 3) * 64 + colK] = kv.w;
            int rowV = id >> 4, d4V = (id & 15) * 4;
            *(float4*)&Vs[rowV * 64 + d4V] = *(const float4*)&vp[(size_t)(k0 + rowV) * 64 + d4V];
        }
        __syncthreads();

        float s[4][4];
#pragma unroll
        for (int i = 0; i < 4; i++)
#pragma unroll
            for (int j = 0; j < 4; j++) s[i][j] = 0.0f;
#pragma unroll 8
        for (int d = 0; d < 64; d++) {
            float4 bb = *(const float4*)&KPs[d * 64 + tx * 4];
#pragma unroll
            for (int i = 0; i < 4; i++) {
                float a = Qs[(ty * 4 + i) * 64 + d];
                s[i][0] = fmaf(a, bb.x, s[i][0]);
                s[i][1] = fmaf(a, bb.y, s[i][1]);
                s[i][2] = fmaf(a, bb.z, s[i][2]);
                s[i][3] = fmaf(a, bb.w, s[i][3]);
            }
        }
#pragma unroll
        for (int i = 0; i < 4; i++) {
            float4 lb = *(const float4*)&lbp[(size_t)(q0 + ty * 4 + i) * 512 + k0 + tx * 4];
            s[i][0] = s[i][0] * 0.125f + lb.x;
            s[i][1] = s[i][1] * 0.125f + lb.y;
            s[i][2] = s[i][2] * 0.125f + lb.z;
            s[i][3] = s[i][3] * 0.125f + lb.w;
        }
#pragma unroll
        for (int i = 0; i < 4; i++) {
            float rm = fmaxf(fmaxf(s[i][0], s[i][1]), fmaxf(s[i][2], s[i][3]));
#pragma unroll
            for (int off = 8; off; off >>= 1)
                rm = fmaxf(rm, __shfl_xor_sync(0xffffffffu, rm, off, 16));
            float mn = fmaxf(m_i[i], rm);
            float corr = __expf(m_i[i] - mn);
            m_i[i] = mn;
            float ps = 0.0f;
#pragma unroll
            for (int j = 0; j < 4; j++) { s[i][j] = __expf(s[i][j] - mn); ps += s[i][j]; }
#pragma unroll
            for (int off = 8; off; off >>= 1)
                ps += __shfl_xor_sync(0xffffffffu, ps, off, 16);
            l_i[i] = l_i[i] * corr + ps;
#pragma unroll
            for (int j = 0; j < 4; j++) o[i][j] *= corr;
        }
        __syncthreads();
#pragma unroll
        for (int i = 0; i < 4; i++)
            *(float4*)&KPs[(ty * 4 + i) * 64 + tx * 4] =
                make_float4(s[i][0], s[i][1], s[i][2], s[i][3]);
        __syncthreads();
#pragma unroll 8
        for (int c = 0; c < 64; c++) {
            float4 vv = *(const float4*)&Vs[c * 64 + tx * 4];
#pragma unroll
            for (int i = 0; i < 4; i++) {
                float a = KPs[(ty * 4 + i) * 64 + c];
                o[i][0] = fmaf(a, vv.x, o[i][0]);
                o[i][1] = fmaf(a, vv.y, o[i][1]);
                o[i][2] = fmaf(a, vv.z, o[i][2]);
                o[i][3] = fmaf(a, vv.w, o[i][3]);
            }
        }
        __syncthreads();
    }

    int b = bh >> 4, h = bh & 15;
#pragma unroll
    for (int i = 0; i < 4; i++) {
        float inv = 1.0f / l_i[i];
        float4 ov = make_float4(o[i][0] * inv, o[i][1] * inv, o[i][2] * inv, o[i][3] * inv);
        *(float4*)&g_att[(size_t)(b * 512 + q0 + ty * 4 + i) * 1024 + h * 64 + tx * 4] = ov;
    }
}

// ---------------- launch ------------------------------------------------------
extern "C" void kernel_launch(void* const* d_in, const int* in_sizes, int n_in,
                              void* d_out, int out_size) {
    (void)in_sizes; (void)n_in; (void)out_size;
    const float* queries = (const float*)d_in[0];
    const float* keys    = (const float*)d_in[1];
    const float* values  = (const float*)d_in[2];
    const float* boxes   = (const float*)d_in[3];
    const float* Wq = (const float*)d_in[4];
    const float* bq = (const float*)d_in[5];
    const float* Wk = (const float*)d_in[6];
    const float* bk = (const float*)d_in[7];
    const float* Wv = (const float*)d_in[8];
    const float* bv = (const float*)d_in[9];
    const float* Wo = (const float*)d_in[10];
    const float* bo = (const float*)d_in[11];
    const float* Wg = (const float*)d_in[12];
    const float* bg = (const float*)d_in[13];
    float* out = (float*)d_out;

    cudaFuncSetAttribute(mma_gemm_kernel,
                         cudaFuncAttributeMaxDynamicSharedMemorySize, MG_SMEM);

    boxfeat_kernel<<<16, 256>>>(boxes);
    bias_kernel<<<8192, 256>>>(Wg, bg);
    // fused QKV projections (z selects)
    mma_gemm_kernel<<<dim3(32, 8, 3), 256, MG_SMEM>>>(
        queries, Wq, bq, nullptr,
        keys,    Wk, bk,
        values,  Wv, bv,
        /*a_sel=*/0, /*c_sel_base=*/1, /*mode=*/1);
    attn_kernel<<<dim3(8, 128), 256>>>();
    // output projection (A = g_att via a_sel)
    mma_gemm_kernel<<<dim3(32, 8, 1), 256, MG_SMEM>>>(
        nullptr, Wo, bo, out,
        nullptr, nullptr, nullptr,
        nullptr, nullptr, nullptr,
        /*a_sel=*/1, /*c_sel_base=*/0, /*mode=*/0);
}

// round 5
// speedup vs baseline: 2.1526x; 1.2789x over previous
#include <cuda_runtime.h>
#include <cuda_bf16.h>
#include <cstdint>

#define Bsz 8
#define Nsq 512
#define DM_ 1024
#define Hh 16
#define DK 64

// ---------------- scratch (static device arrays; no allocation) --------------
__device__ float g_logb[(size_t)Bsz*Hh*Nsq*Nsq]; // (b,h,n,m)
__device__ float g_att[Bsz*Nsq*DM_];             // (b,n, h*dv)
__device__ float g_boxf[Bsz*Nsq*8];              // cx,cy,w,h,logw,logh
// packed bf16x2 hi/lo projections, layout (b,h,n,d) pairs: idx = ((bh*512+n)*64+d)/2
__device__ uint32_t g_qh[Bsz*Hh*Nsq*DK/2];
__device__ uint32_t g_ql[Bsz*Hh*Nsq*DK/2];
__device__ uint32_t g_kh[Bsz*Hh*Nsq*DK/2];
__device__ uint32_t g_kl[Bsz*Hh*Nsq*DK/2];
__device__ uint32_t g_vh[Bsz*Hh*Nsq*DK/2];
__device__ uint32_t g_vl[Bsz*Hh*Nsq*DK/2];

// ---------------- helpers ----------------------------------------------------
__device__ __forceinline__ uint32_t smem_u32(const void* p) {
    uint32_t a;
    asm("{ .reg .u64 t; cvta.to.shared.u64 t, %1; cvt.u32.u64 %0, t; }" : "=r"(a) : "l"(p));
    return a;
}

#define LDSM4(r, a) \
    asm volatile("ldmatrix.sync.aligned.m8n8.x4.shared.b16 {%0,%1,%2,%3}, [%4];" \
        : "=r"((r)[0]), "=r"((r)[1]), "=r"((r)[2]), "=r"((r)[3]) : "r"(a))
#define LDSM4T(r, a) \
    asm volatile("ldmatrix.sync.aligned.m8n8.x4.trans.shared.b16 {%0,%1,%2,%3}, [%4];" \
        : "=r"((r)[0]), "=r"((r)[1]), "=r"((r)[2]), "=r"((r)[3]) : "r"(a))

#define CP_ASYNC16(dst, src) \
    asm volatile("cp.async.cg.shared.global [%0], [%1], 16;" :: "r"(dst), "l"(src) : "memory")
#define CP_COMMIT() asm volatile("cp.async.commit_group;" ::: "memory")
#define CP_WAIT(n)  asm volatile("cp.async.wait_group %0;" :: "n"(n) : "memory")

__device__ __forceinline__ void mma16816(float* c, const uint32_t* a, const uint32_t* b) {
    asm volatile("mma.sync.aligned.m16n8k16.row.col.f32.bf16.bf16.f32 "
        "{%0,%1,%2,%3}, {%4,%5,%6,%7}, {%8,%9}, {%0,%1,%2,%3};"
        : "+f"(c[0]), "+f"(c[1]), "+f"(c[2]), "+f"(c[3])
        : "r"(a[0]), "r"(a[1]), "r"(a[2]), "r"(a[3]), "r"(b[0]), "r"(b[1]));
}

// split two floats into packed bf16x2 hi + bf16x2 lo (residual)
__device__ __forceinline__ void split2(float x, float y, uint32_t& hi, uint32_t& lo) {
    asm("cvt.rn.bf16x2.f32 %0, %1, %2;" : "=r"(hi) : "f"(y), "f"(x));
    float fx = __uint_as_float(hi << 16);
    float fy = __uint_as_float(hi & 0xffff0000u);
    asm("cvt.rn.bf16x2.f32 %0, %1, %2;" : "=r"(lo) : "f"(y - fy), "f"(x - fx));
}

// ---------------- box feature precompute ------------------------------------
__global__ void boxfeat_kernel(const float* __restrict__ boxes) {
    int i = blockIdx.x * 256 + threadIdx.x;            // < B*N = 4096
    float4 bx = *(const float4*)(boxes + (size_t)i * 4);
    float cx = (bx.x + bx.z) * 0.5f;
    float cy = (bx.y + bx.w) * 0.5f;
    float w  = (bx.z - bx.x) + 1.0f;
    float h  = (bx.w - bx.y) + 1.0f;
    float* o = g_boxf + (size_t)i * 8;
    o[0] = cx; o[1] = cy; o[2] = w; o[3] = h;
    o[4] = __logf(w); o[5] = __logf(h);
}

// ---------------- geometry bias:  logb[b,h,n,m] ------------------------------
__global__ __launch_bounds__(256) void bias_kernel(const float* __restrict__ Wg,
                                                   const float* __restrict__ bg) {
    __shared__ float Wgs[64 * 16];   // [emb_idx][h]
    __shared__ float bgs[16];
    int tid = threadIdx.x;
    for (int i = tid; i < 1024; i += 256) {
        int h = i >> 6, idx = i & 63;
        Wgs[idx * 16 + h] = Wg[i];
    }
    if (tid < 16) bgs[tid] = bg[tid];
    __syncthreads();

    int t = blockIdx.x * 256 + tid;                    // < B*N*N
    int m = t & 511;
    int n = (t >> 9) & 511;
    int b = t >> 18;

    const float* fn = g_boxf + (size_t)(b * 512 + n) * 8;
    const float* fm = g_boxf + (size_t)(b * 512 + m) * 8;
    float cxn = fn[0], cyn = fn[1], wn = fn[2], hn = fn[3], lwn = fn[4], lhn = fn[5];
    float cxm = fm[0], cym = fm[1], lwm = fm[4], lhm = fm[5];

    float pos[4];
    pos[0] = __logf(fmaxf(fabsf(cxn - cxm) / wn, 1e-3f)) * 100.0f;
    pos[1] = __logf(fmaxf(fabsf(cyn - cym) / hn, 1e-3f)) * 100.0f;
    pos[2] = (lwn - lwm) * 100.0f;
    pos[3] = (lhn - lhm) * 100.0f;

    const float DMAT[8] = {1.0f, 0.4216965034f, 0.1778279410f, 0.0749894209f,
                           0.0316227766f, 0.0133352143f, 0.0056234133f, 0.0023713737f};

    float acc[16];
#pragma unroll
    for (int h = 0; h < 16; h++) acc[h] = 0.0f;

#pragma unroll
    for (int d = 0; d < 4; d++) {
#pragma unroll
        for (int j = 0; j < 8; j++) {
            float s, c;
            __sincosf(pos[d] * DMAT[j], &s, &c);
            int idx = d * 8 + j;
            const float* ws = &Wgs[idx * 16];
            const float* wc = &Wgs[(32 + idx) * 16];
#pragma unroll
            for (int h = 0; h < 16; h++)
                acc[h] = fmaf(s, ws[h], fmaf(c, wc[h], acc[h]));
        }
    }

    size_t base = (size_t)(b * 16) * 262144 + (size_t)n * 512 + m;
#pragma unroll
    for (int h = 0; h < 16; h++) {
        float g = acc[h] + bgs[h];
        g = fmaxf(g, 1e-6f);
        g_logb[base + (size_t)h * 262144] = __logf(g);
    }
}

// ============ mma.sync GEMM: C[M,1024] = A[M,1024] @ W[1024,1024]^T + bias ====
static constexpr int STAGE_B = 4 * 128 * 80;          // 40960
static constexpr int MG_SMEM = 2 * STAGE_B;           // 81920

__global__ __launch_bounds__(256) void mma_gemm_kernel(
        const float* __restrict__ A0, const float* __restrict__ W0,
        const float* __restrict__ b0p, float* __restrict__ C0,
        const float* __restrict__ A1, const float* __restrict__ W1,
        const float* __restrict__ b1p,
        const float* __restrict__ A2, const float* __restrict__ W2,
        const float* __restrict__ b2p,
        int a_sel, int mode) {
    extern __shared__ char smem[];
    int z = blockIdx.z;
    const float* A;
    if (a_sel == 1) A = g_att;
    else A = (z == 0) ? A0 : (z == 1) ? A1 : A2;
    const float* W = (z == 0) ? W0 : (z == 1) ? W1 : W2;
    const float* bias = (z == 0) ? b0p : (z == 1) ? b1p : b2p;

    uint32_t sbase = smem_u32(smem);
    int tid = threadIdx.x;
    int lane = tid & 31, wid = tid >> 5;
    int wm = wid & 3, wn = wid >> 2;           // warp tile: rows wm*32, cols wn*64
    int m0 = blockIdx.x * 128, n0 = blockIdx.y * 128;

    int gr = tid >> 3, gq = tid & 7;           // gr 0..31 (+32*p), gq 0..7

    uint32_t aOff = (uint32_t)(wm * 32 + (lane & 15)) * 80 + (uint32_t)(lane >> 4) * 16;
    uint32_t bOff = (uint32_t)(wn * 64 + (lane & 7) + ((lane >> 4) & 1) * 8) * 80
                  + (uint32_t)((lane >> 3) & 1) * 16;

    float acc[2][8][4];
#pragma unroll
    for (int i = 0; i < 2; i++)
#pragma unroll
        for (int j = 0; j < 8; j++)
#pragma unroll
            for (int q = 0; q < 4; q++) acc[i][j][q] = 0.0f;

    float4 stA[4], stB[4];
#pragma unroll
    for (int p = 0; p < 4; p++) {
        int r = gr + p * 32;
        stA[p] = *(const float4*)(A + (size_t)(m0 + r) * 1024 + gq * 4);
        stB[p] = *(const float4*)(W + (size_t)(n0 + r) * 1024 + gq * 4);
    }

    for (int c = 0; c < 32; ++c) {
        int stage = c & 1;
        {
            char* sb = smem + stage * STAGE_B;
#pragma unroll
            for (int p = 0; p < 4; p++) {
                int r = gr + p * 32;
                uint32_t off = (uint32_t)r * 80 + (uint32_t)gq * 8;
                uint32_t h0, l0, h1, l1;
                split2(stA[p].x, stA[p].y, h0, l0);
                split2(stA[p].z, stA[p].w, h1, l1);
                *(uint2*)(sb + off)         = make_uint2(h0, h1);
                *(uint2*)(sb + 10240 + off) = make_uint2(l0, l1);
                split2(stB[p].x, stB[p].y, h0, l0);
                split2(stB[p].z, stB[p].w, h1, l1);
                *(uint2*)(sb + 20480 + off) = make_uint2(h0, h1);
                *(uint2*)(sb + 30720 + off) = make_uint2(l0, l1);
            }
        }
        __syncthreads();

        if (c + 1 < 32) {
            int k0 = (c + 1) * 32;
#pragma unroll
            for (int p = 0; p < 4; p++) {
                int r = gr + p * 32;
                stA[p] = *(const float4*)(A + (size_t)(m0 + r) * 1024 + k0 + gq * 4);
                stB[p] = *(const float4*)(W + (size_t)(n0 + r) * 1024 + k0 + gq * 4);
            }
        }

        uint32_t base = sbase + stage * STAGE_B;
#pragma unroll
        for (int k16 = 0; k16 < 2; k16++) {
            uint32_t ah[2][4], al[2][4];
#pragma unroll
            for (int mt = 0; mt < 2; mt++) {
                uint32_t ao = base + aOff + (uint32_t)mt * (16 * 80) + (uint32_t)k16 * 32;
                LDSM4(ah[mt], ao);
                LDSM4(al[mt], ao + 10240);
            }
#pragma unroll
            for (int ntp = 0; ntp < 4; ntp++) {
                uint32_t bh[4], bl[4];
                uint32_t bo = base + 20480 + bOff + (uint32_t)ntp * (16 * 80) + (uint32_t)k16 * 32;
                LDSM4(bh, bo);
                LDSM4(bl, bo + 10240);
#pragma unroll
                for (int mt = 0; mt < 2; mt++) {
#pragma unroll
                    for (int h8 = 0; h8 < 2; h8++) {
                        float* cc = acc[mt][ntp * 2 + h8];
                        mma16816(cc, ah[mt], bh + h8 * 2);
                        mma16816(cc, ah[mt], bl + h8 * 2);
                        mma16816(cc, al[mt], bh + h8 * 2);
                    }
                }
            }
        }
        __syncthreads();
    }

    // ---- epilogue ----
    float qs = (mode == 1 && z == 0) ? 0.125f : 1.0f;  // fold 1/sqrt(dk) into Q
#pragma unroll
    for (int mt = 0; mt < 2; mt++) {
#pragma unroll
        for (int nt8 = 0; nt8 < 8; nt8++) {
            const float* cc = acc[mt][nt8];
            int row = m0 + wm * 32 + mt * 16 + (lane >> 2);
            int col = n0 + wn * 64 + nt8 * 8 + (lane & 3) * 2;
            float bx = bias[col], by = bias[col + 1];
            float2 v0 = make_float2((cc[0] + bx) * qs, (cc[1] + by) * qs);
            float2 v1 = make_float2((cc[2] + bx) * qs, (cc[3] + by) * qs);
            if (mode == 1) {
                uint32_t* Ph = (z == 0) ? g_qh : (z == 1) ? g_kh : g_vh;
                uint32_t* Pl = (z == 0) ? g_ql : (z == 1) ? g_kl : g_vl;
                int h = col >> 6, d = col & 63;
                int bb = row >> 9, s = row & 511;
                size_t p0 = (((size_t)((bb * 16 + h) * 512 + s)) * 64 + d) >> 1;
                int bb2 = (row + 8) >> 9, s2 = (row + 8) & 511;
                size_t p1 = (((size_t)((bb2 * 16 + h) * 512 + s2)) * 64 + d) >> 1;
                uint32_t hi, lo;
                split2(v0.x, v0.y, hi, lo);
                Ph[p0] = hi; Pl[p0] = lo;
                split2(v1.x, v1.y, hi, lo);
                Ph[p1] = hi; Pl[p1] = lo;
            } else {
                *(float2*)&C0[(size_t)row * 1024 + col] = v0;
                *(float2*)&C0[(size_t)(row + 8) * 1024 + col] = v1;
            }
        }
    }
}

// ============ tensor-core flash attention with geometry bias ==================
// 128 threads, 4 warps (each m16 over q), q-tile 64, k-chunks of 64.
// Buffers: 2 x 36864 B; per buf: Kh@0 Kl@9216 Vh@18432 Vl@27648, rows 144B.
static constexpr uint32_t ABUF = 36864;
static constexpr int ATTN_SMEM = 2 * 36864;   // 73728

__global__ __launch_bounds__(128) void attn_mma_kernel() {
    extern __shared__ __align__(16) char asmem[];
    uint32_t sbase = smem_u32(asmem);
    int tid = threadIdx.x, lane = tid & 31, w = tid >> 5;
    int q0 = blockIdx.x * 64, bh = blockIdx.y;
    size_t bhb = (size_t)bh * 65536;    // bytes per (b,h) slab: 512*64*2
    const char* pqh = (const char*)g_qh + bhb + (size_t)q0 * 128;
    const char* pql = (const char*)g_ql + bhb + (size_t)q0 * 128;
    const char* pkh = (const char*)g_kh + bhb;
    const char* pkl = (const char*)g_kl + bhb;
    const char* pvh = (const char*)g_vh + bhb;
    const char* pvl = (const char*)g_vl + bhb;
    const float* lbp = g_logb + (size_t)bh * 262144;

    // stage Q into buf1 (hi @ +0, lo @ +9216)
#pragma unroll
    for (int p = 0; p < 4; p++) {
        int id = tid + p * 128, row = id >> 3, seg = id & 7;
        uint32_t d = sbase + ABUF + (uint32_t)row * 144 + (uint32_t)seg * 16;
        int so = row * 128 + seg * 16;
        CP_ASYNC16(d, pqh + so);
        CP_ASYNC16(d + 9216, pql + so);
    }
    CP_COMMIT();
    // chunk 0 into buf0
#pragma unroll
    for (int p = 0; p < 4; p++) {
        int id = tid + p * 128, row = id >> 3, seg = id & 7;
        uint32_t d = sbase + (uint32_t)row * 144 + (uint32_t)seg * 16;
        int so = row * 128 + seg * 16;
        CP_ASYNC16(d,         pkh + so);
        CP_ASYNC16(d + 9216,  pkl + so);
        CP_ASYNC16(d + 18432, pvh + so);
        CP_ASYNC16(d + 27648, pvl + so);
    }
    CP_COMMIT();
    CP_WAIT(1);               // Q staged
    __syncthreads();

    uint32_t qh[4][4], ql[4][4];
    {
        uint32_t aOff = (uint32_t)(w * 16 + (lane & 15)) * 144 + (uint32_t)(lane >> 4) * 16;
#pragma unroll
        for (int k16 = 0; k16 < 4; k16++) {
            LDSM4(qh[k16], sbase + ABUF + aOff + k16 * 32);
            LDSM4(ql[k16], sbase + ABUF + 9216 + aOff + k16 * 32);
        }
    }
    __syncthreads();          // Q region may now be overwritten (chunk1)

    float o[8][4];
#pragma unroll
    for (int t = 0; t < 8; t++)
#pragma unroll
        for (int q = 0; q < 4; q++) o[t][q] = 0.0f;
    float m0 = -1e30f, m1 = -1e30f, l0 = 0.0f, l1 = 0.0f;

    uint32_t bOffK = (uint32_t)((lane & 7) + ((lane >> 4) & 1) * 8) * 144
                   + (uint32_t)((lane >> 3) & 1) * 16;
    uint32_t vOff  = (uint32_t)((lane & 7) + ((lane >> 3) & 1) * 8) * 144
                   + (uint32_t)(lane >> 4) * 16;

    for (int c = 0; c < 8; c++) {
        if (c < 7) {
            int k0 = (c + 1) * 64;
            uint32_t bb = sbase + (uint32_t)((c + 1) & 1) * ABUF;
#pragma unroll
            for (int p = 0; p < 4; p++) {
                int id = tid + p * 128, row = id >> 3, seg = id & 7;
                uint32_t d = bb + (uint32_t)row * 144 + (uint32_t)seg * 16;
                int so = (k0 + row) * 128 + seg * 16;
                CP_ASYNC16(d,         pkh + so);
                CP_ASYNC16(d + 9216,  pkl + so);
                CP_ASYNC16(d + 18432, pvh + so);
                CP_ASYNC16(d + 27648, pvl + so);
            }
            CP_COMMIT();
            CP_WAIT(1);
        } else {
            CP_WAIT(0);
        }
        __syncthreads();
        uint32_t sb = sbase + (uint32_t)(c & 1) * ABUF;

        // prefetch logb for this tile (rows lane/4, +8; cols pairs)
        const float* lp = lbp + (size_t)(q0 + w * 16 + (lane >> 2)) * 512
                        + c * 64 + (lane & 3) * 2;
        float2 lbA[8], lbB[8];
#pragma unroll
        for (int t = 0; t < 8; t++) {
            lbA[t] = *(const float2*)(lp + t * 8);
            lbB[t] = *(const float2*)(lp + 4096 + t * 8);
        }

        // S = Q K^T  (Q pre-scaled by 0.125)
        float s[8][4];
#pragma unroll
        for (int t = 0; t < 8; t++)
#pragma unroll
            for (int q = 0; q < 4; q++) s[t][q] = 0.0f;
#pragma unroll
        for (int k16 = 0; k16 < 4; k16++) {
#pragma unroll
            for (int ntp = 0; ntp < 4; ntp++) {
                uint32_t bh4[4], bl4[4];
                uint32_t bo = sb + bOffK + (uint32_t)ntp * 2304 + (uint32_t)k16 * 32;
                LDSM4(bh4, bo);
                LDSM4(bl4, bo + 9216);
#pragma unroll
                for (int h8 = 0; h8 < 2; h8++) {
                    float* cc = s[ntp * 2 + h8];
                    mma16816(cc, qh[k16], bh4 + h8 * 2);
                    mma16816(cc, ql[k16], bh4 + h8 * 2);
                    mma16816(cc, qh[k16], bl4 + h8 * 2);
                }
            }
        }

        // bias + online softmax (rows split: regs 0,1 -> row lane/4; 2,3 -> +8)
        float rm0 = -1e30f, rm1 = -1e30f;
#pragma unroll
        for (int t = 0; t < 8; t++) {
            s[t][0] += lbA[t].x; s[t][1] += lbA[t].y;
            s[t][2] += lbB[t].x; s[t][3] += lbB[t].y;
            rm0 = fmaxf(rm0, fmaxf(s[t][0], s[t][1]));
            rm1 = fmaxf(rm1, fmaxf(s[t][2], s[t][3]));
        }
        rm0 = fmaxf(rm0, __shfl_xor_sync(0xffffffffu, rm0, 1, 4));
        rm0 = fmaxf(rm0, __shfl_xor_sync(0xffffffffu, rm0, 2, 4));
        rm1 = fmaxf(rm1, __shfl_xor_sync(0xffffffffu, rm1, 1, 4));
        rm1 = fmaxf(rm1, __shfl_xor_sync(0xffffffffu, rm1, 2, 4));
        float mn0 = fmaxf(m0, rm0), mn1 = fmaxf(m1, rm1);
        float c0 = __expf(m0 - mn0), c1 = __expf(m1 - mn1);
        m0 = mn0; m1 = mn1;
        float ps0 = 0.0f, ps1 = 0.0f;
#pragma unroll
        for (int t = 0; t < 8; t++) {
            s[t][0] = __expf(s[t][0] - mn0); ps0 += s[t][0];
            s[t][1] = __expf(s[t][1] - mn0); ps0 += s[t][1];
            s[t][2] = __expf(s[t][2] - mn1); ps1 += s[t][2];
            s[t][3] = __expf(s[t][3] - mn1); ps1 += s[t][3];
        }
        ps0 += __shfl_xor_sync(0xffffffffu, ps0, 1, 4);
        ps0 += __shfl_xor_sync(0xffffffffu, ps0, 2, 4);
        ps1 += __shfl_xor_sync(0xffffffffu, ps1, 1, 4);
        ps1 += __shfl_xor_sync(0xffffffffu, ps1, 2, 4);
        l0 = l0 * c0 + ps0; l1 = l1 * c1 + ps1;
#pragma unroll
        for (int t = 0; t < 8; t++) {
            o[t][0] *= c0; o[t][1] *= c0; o[t][2] *= c1; o[t][3] *= c1;
        }

        // P accum -> A fragments (register repack), hi/lo split
        uint32_t ph[4][4], pl[4][4];
#pragma unroll
        for (int j = 0; j < 4; j++) {
            split2(s[2*j][0],   s[2*j][1],   ph[j][0], pl[j][0]);
            split2(s[2*j][2],   s[2*j][3],   ph[j][1], pl[j][1]);
            split2(s[2*j+1][0], s[2*j+1][1], ph[j][2], pl[j][2]);
            split2(s[2*j+1][2], s[2*j+1][3], ph[j][3], pl[j][3]);
        }

        // O += P V  (V fragments via ldmatrix.trans from [key][dv] layout)
#pragma unroll
        for (int j = 0; j < 4; j++) {
#pragma unroll
            for (int np = 0; np < 4; np++) {
                uint32_t vh4[4], vl4[4];
                uint32_t vo = sb + 18432 + vOff + (uint32_t)j * 2304 + (uint32_t)np * 32;
                LDSM4T(vh4, vo);
                LDSM4T(vl4, vo + 9216);
#pragma unroll
                for (int h8 = 0; h8 < 2; h8++) {
                    float* cc = o[np * 2 + h8];
                    mma16816(cc, ph[j], vh4 + h8 * 2);
                    mma16816(cc, pl[j], vh4 + h8 * 2);
                    mma16816(cc, ph[j], vl4 + h8 * 2);
                }
            }
        }
        __syncthreads();
    }

    // epilogue: normalize, scatter to g_att (b, n, h*64)
    float i0 = 1.0f / l0, i1 = 1.0f / l1;
    int b = bh >> 4, hh = bh & 15;
    int r0 = q0 + w * 16 + (lane >> 2);
    float* ob0 = g_att + (size_t)(b * 512 + r0) * 1024 + hh * 64 + (lane & 3) * 2;
    float* ob1 = ob0 + (size_t)8 * 1024;
#pragma unroll
    for (int t = 0; t < 8; t++) {
        *(float2*)(ob0 + t * 8) = make_float2(o[t][0] * i0, o[t][1] * i0);
        *(float2*)(ob1 + t * 8) = make_float2(o[t][2] * i1, o[t][3] * i1);
    }
}

// ---------------- launch ------------------------------------------------------
extern "C" void kernel_launch(void* const* d_in, const int* in_sizes, int n_in,
                              void* d_out, int out_size) {
    (void)in_sizes; (void)n_in; (void)out_size;
    const float* queries = (const float*)d_in[0];
    const float* keys    = (const float*)d_in[1];
    const float* values  = (const float*)d_in[2];
    const float* boxes   = (const float*)d_in[3];
    const float* Wq = (const float*)d_in[4];
    const float* bq = (const float*)d_in[5];
    const float* Wk = (const float*)d_in[6];
    const float* bk = (const float*)d_in[7];
    const float* Wv = (const float*)d_in[8];
    const float* bv = (const float*)d_in[9];
    const float* Wo = (const float*)d_in[10];
    const float* bo = (const float*)d_in[11];
    const float* Wg = (const float*)d_in[12];
    const float* bg = (const float*)d_in[13];
    float* out = (float*)d_out;

    cudaFuncSetAttribute(mma_gemm_kernel,
                         cudaFuncAttributeMaxDynamicSharedMemorySize, MG_SMEM);
    cudaFuncSetAttribute(attn_mma_kernel,
                         cudaFuncAttributeMaxDynamicSharedMemorySize, ATTN_SMEM);

    boxfeat_kernel<<<16, 256>>>(boxes);
    bias_kernel<<<8192, 256>>>(Wg, bg);
    mma_gemm_kernel<<<dim3(32, 8, 3), 256, MG_SMEM>>>(
        queries, Wq, bq, nullptr,
        keys,    Wk, bk,
        values,  Wv, bv,
        /*a_sel=*/0, /*mode=*/1);
    attn_mma_kernel<<<dim3(8, 128), 128, ATTN_SMEM>>>();
    mma_gemm_kernel<<<dim3(32, 8, 1), 256, MG_SMEM>>>(
        nullptr, Wo, bo, out,
        nullptr, nullptr, nullptr,
        nullptr, nullptr, nullptr,
        /*a_sel=*/1, /*mode=*/0);
}

// round 7
// speedup vs baseline: 2.1624x; 1.0045x over previous
#include <cuda_runtime.h>
#include <cuda_bf16.h>
#include <cuda_fp16.h>
#include <cstdint>

#define Bsz 8
#define Nsq 512
#define DM_ 1024
#define Hh 16
#define DK 64

// ---------------- scratch (static device arrays; no allocation) --------------
__device__ __half g_logb[(size_t)Bsz*Hh*Nsq*Nsq]; // (b,h,n,m) fp16
__device__ float g_boxf[Bsz*Nsq*8];               // cx,cy,w,h,logw,logh
// packed bf16x2 hi/lo projections (b,h,n,d): idx = ((bh*512+n)*64+d)/2
__device__ uint32_t g_qh[Bsz*Hh*Nsq*DK/2];
__device__ uint32_t g_ql[Bsz*Hh*Nsq*DK/2];
__device__ uint32_t g_kh[Bsz*Hh*Nsq*DK/2];
__device__ uint32_t g_kl[Bsz*Hh*Nsq*DK/2];
__device__ uint32_t g_vh[Bsz*Hh*Nsq*DK/2];
__device__ uint32_t g_vl[Bsz*Hh*Nsq*DK/2];
// pre-converted GEMM operands (bf16 hi/lo pairs, row = 512 uint32)
__device__ uint32_t g_inh[3u*4096*512];   // queries/keys/values
__device__ uint32_t g_inl[3u*4096*512];
__device__ uint32_t g_wh[4u*1024*512];    // Wq,Wk,Wv,Wo
__device__ uint32_t g_wl[4u*1024*512];
__device__ uint32_t g_oh[4096u*512];      // attention output (b,n,h*64)
__device__ uint32_t g_ol[4096u*512];

// ---------------- helpers ----------------------------------------------------
__device__ __forceinline__ uint32_t smem_u32(const void* p) {
    uint32_t a;
    asm("{ .reg .u64 t; cvta.to.shared.u64 t, %1; cvt.u32.u64 %0, t; }" : "=r"(a) : "l"(p));
    return a;
}

#define LDSM4(r, a) \
    asm volatile("ldmatrix.sync.aligned.m8n8.x4.shared.b16 {%0,%1,%2,%3}, [%4];" \
        : "=r"((r)[0]), "=r"((r)[1]), "=r"((r)[2]), "=r"((r)[3]) : "r"(a))
#define LDSM4T(r, a) \
    asm volatile("ldmatrix.sync.aligned.m8n8.x4.trans.shared.b16 {%0,%1,%2,%3}, [%4];" \
        : "=r"((r)[0]), "=r"((r)[1]), "=r"((r)[2]), "=r"((r)[3]) : "r"(a))

#define CP_ASYNC16(dst, src) \
    asm volatile("cp.async.cg.shared.global [%0], [%1], 16;" :: "r"(dst), "l"(src) : "memory")
#define CP_COMMIT() asm volatile("cp.async.commit_group;" ::: "memory")
#define CP_WAIT(n)  asm volatile("cp.async.wait_group %0;" :: "n"(n) : "memory")

__device__ __forceinline__ void mma16816(float* c, const uint32_t* a, const uint32_t* b) {
    asm volatile("mma.sync.aligned.m16n8k16.row.col.f32.bf16.bf16.f32 "
        "{%0,%1,%2,%3}, {%4,%5,%6,%7}, {%8,%9}, {%0,%1,%2,%3};"
        : "+f"(c[0]), "+f"(c[1]), "+f"(c[2]), "+f"(c[3])
        : "r"(a[0]), "r"(a[1]), "r"(a[2]), "r"(a[3]), "r"(b[0]), "r"(b[1]));
}

__device__ __forceinline__ void split2(float x, float y, uint32_t& hi, uint32_t& lo) {
    asm("cvt.rn.bf16x2.f32 %0, %1, %2;" : "=r"(hi) : "f"(y), "f"(x));
    float fx = __uint_as_float(hi << 16);
    float fy = __uint_as_float(hi & 0xffff0000u);
    asm("cvt.rn.bf16x2.f32 %0, %1, %2;" : "=r"(lo) : "f"(y - fy), "f"(x - fx));
}

// ---------------- f32 -> bf16 hi/lo pre-conversion ---------------------------
// dst_sel: 0..2 -> g_inh/g_inl slot (4096x1024), 3..6 -> g_wh/g_wl slot (1024x1024)
__global__ void conv_kernel(const float* __restrict__ src, int dst_sel) {
    uint32_t* dh; uint32_t* dl;
    if (dst_sel < 3) {
        dh = g_inh + (size_t)dst_sel * 2097152;
        dl = g_inl + (size_t)dst_sel * 2097152;
    } else {
        dh = g_wh + (size_t)(dst_sel - 3) * 524288;
        dl = g_wl + (size_t)(dst_sel - 3) * 524288;
    }
    size_t i = (size_t)blockIdx.x * 256 + threadIdx.x;
    float4 v = *(const float4*)(src + i * 4);
    uint32_t h0, l0, h1, l1;
    split2(v.x, v.y, h0, l0);
    split2(v.z, v.w, h1, l1);
    *(uint2*)(dh + i * 2) = make_uint2(h0, h1);
    *(uint2*)(dl + i * 2) = make_uint2(l0, l1);
}

// ---------------- box feature precompute ------------------------------------
__global__ void boxfeat_kernel(const float* __restrict__ boxes) {
    int i = blockIdx.x * 256 + threadIdx.x;            // < B*N = 4096
    float4 bx = *(const float4*)(boxes + (size_t)i * 4);
    float cx = (bx.x + bx.z) * 0.5f;
    float cy = (bx.y + bx.w) * 0.5f;
    float w  = (bx.z - bx.x) + 1.0f;
    float h  = (bx.w - bx.y) + 1.0f;
    float* o = g_boxf + (size_t)i * 8;
    o[0] = cx; o[1] = cy; o[2] = w; o[3] = h;
    o[4] = __logf(w); o[5] = __logf(h);
}

// ---------------- geometry bias:  logb[b,h,n,m]  (fp16 out) -------------------
__global__ __launch_bounds__(256) void bias_kernel(const float* __restrict__ Wg,
                                                   const float* __restrict__ bg) {
    __shared__ float Wgs[64 * 16];   // [emb_idx][h]
    __shared__ float bgs[16];
    int tid = threadIdx.x;
    for (int i = tid; i < 1024; i += 256) {
        int h = i >> 6, idx = i & 63;
        Wgs[idx * 16 + h] = Wg[i];
    }
    if (tid < 16) bgs[tid] = bg[tid];
    __syncthreads();

    int t = blockIdx.x * 256 + tid;                    // < B*N*N
    int m = t & 511;
    int n = (t >> 9) & 511;
    int b = t >> 18;

    const float* fn = g_boxf + (size_t)(b * 512 + n) * 8;
    const float* fm = g_boxf + (size_t)(b * 512 + m) * 8;
    float cxn = fn[0], cyn = fn[1], wn = fn[2], hn = fn[3], lwn = fn[4], lhn = fn[5];
    float cxm = fm[0], cym = fm[1], lwm = fm[4], lhm = fm[5];

    float pos[4];
    pos[0] = __logf(fmaxf(fabsf(cxn - cxm) / wn, 1e-3f)) * 100.0f;
    pos[1] = __logf(fmaxf(fabsf(cyn - cym) / hn, 1e-3f)) * 100.0f;
    pos[2] = (lwn - lwm) * 100.0f;
    pos[3] = (lhn - lhm) * 100.0f;

    const float DMAT[8] = {1.0f, 0.4216965034f, 0.1778279410f, 0.0749894209f,
                           0.0316227766f, 0.0133352143f, 0.0056234133f, 0.0023713737f};

    float acc[16];
#pragma unroll
    for (int h = 0; h < 16; h++) acc[h] = 0.0f;

#pragma unroll
    for (int d = 0; d < 4; d++) {
#pragma unroll
        for (int j = 0; j < 8; j++) {
            float s, c;
            __sincosf(pos[d] * DMAT[j], &s, &c);
            int idx = d * 8 + j;
            const float* ws = &Wgs[idx * 16];
            const float* wc = &Wgs[(32 + idx) * 16];
#pragma unroll
            for (int h = 0; h < 16; h++)
                acc[h] = fmaf(s, ws[h], fmaf(c, wc[h], acc[h]));
        }
    }

    size_t base = (size_t)(b * 16) * 262144 + (size_t)n * 512 + m;
#pragma unroll
    for (int h = 0; h < 16; h++) {
        float g = acc[h] + bgs[h];
        g = fmaxf(g, 1e-6f);
        g_logb[base + (size_t)h * 262144] = __float2half_rn(__logf(g));
    }
}

// ============ mma.sync GEMM on pre-converted bf16 hi/lo operands ==============
// C[M,1024] = A @ W^T + bias. 128x128 CTA tile, 8 warps of 32x64, k-chunk 32.
// Per stage: Ah,Al,Bh,Bl each 128 rows x 80B = 40960 B; 2 stages, cp.async.
static constexpr int STAGE_B = 4 * 128 * 80;          // 40960
static constexpr int MG_SMEM = 2 * STAGE_B;           // 81920

__global__ __launch_bounds__(256, 2) void mma_gemm_kernel(
        const float* __restrict__ b0p, const float* __restrict__ b1p,
        const float* __restrict__ b2p, float* __restrict__ C0,
        int a_sel, int mode) {
    extern __shared__ char smem[];
    int z = blockIdx.z;
    const uint32_t* Ah;
    const uint32_t* Al;
    if (a_sel) { Ah = g_oh; Al = g_ol; }
    else       { Ah = g_inh + (size_t)z * 2097152; Al = g_inl + (size_t)z * 2097152; }
    int wsel = a_sel ? 3 : z;
    const uint32_t* Wh = g_wh + (size_t)wsel * 524288;
    const uint32_t* Wl = g_wl + (size_t)wsel * 524288;
    const float* bias = (z == 0) ? b0p : (z == 1) ? b1p : b2p;

    uint32_t sbase = smem_u32(smem);
    int tid = threadIdx.x;
    int lane = tid & 31, wid = tid >> 5;
    int wm = wid & 3, wn = wid >> 2;           // warp tile rows wm*32, cols wn*64
    int m0 = blockIdx.x * 128, n0 = blockIdx.y * 128;

    const uint32_t* srcb[4];
    srcb[0] = Ah + (size_t)m0 * 512;
    srcb[1] = Al + (size_t)m0 * 512;
    srcb[2] = Wh + (size_t)n0 * 512;
    srcb[3] = Wl + (size_t)n0 * 512;

    uint32_t aOff = (uint32_t)(wm * 32 + (lane & 15)) * 80 + (uint32_t)(lane >> 4) * 16;
    uint32_t bOff = (uint32_t)(wn * 64 + (lane & 7) + ((lane >> 4) & 1) * 8) * 80
                  + (uint32_t)((lane >> 3) & 1) * 16;

    float acc[2][8][4];
#pragma unroll
    for (int i = 0; i < 2; i++)
#pragma unroll
        for (int j = 0; j < 8; j++)
#pragma unroll
            for (int q = 0; q < 4; q++) acc[i][j][q] = 0.0f;

    // issue chunk 0
    {
        uint32_t bb = sbase;
#pragma unroll
        for (int p = 0; p < 8; p++) {
            int mat = p >> 1;
            int id2 = tid + (p & 1) * 256;     // 0..511
            int row = id2 >> 2, seg = id2 & 3;
            uint32_t dst = bb + (uint32_t)mat * 10240 + (uint32_t)row * 80 + (uint32_t)seg * 16;
            CP_ASYNC16(dst, srcb[mat] + (size_t)row * 512 + seg * 4);
        }
        CP_COMMIT();
    }

    for (int c = 0; c < 32; ++c) {
        if (c + 1 < 32) {
            uint32_t bb = sbase + (uint32_t)((c + 1) & 1) * STAGE_B;
            int k0 = (c + 1) * 16;             // uint32 offset within row
#pragma unroll
            for (int p = 0; p < 8; p++) {
                int mat = p >> 1;
                int id2 = tid + (p & 1) * 256;
                int row = id2 >> 2, seg = id2 & 3;
                uint32_t dst = bb + (uint32_t)mat * 10240 + (uint32_t)row * 80 + (uint32_t)seg * 16;
                CP_ASYNC16(dst, srcb[mat] + (size_t)row * 512 + k0 + seg * 4);
            }
            CP_COMMIT();
            CP_WAIT(1);
        } else {
            CP_WAIT(0);
        }
        __syncthreads();

        uint32_t base = sbase + (uint32_t)(c & 1) * STAGE_B;
#pragma unroll
        for (int k16 = 0; k16 < 2; k16++) {
            uint32_t ah[2][4], al[2][4];
#pragma unroll
            for (int mt = 0; mt < 2; mt++) {
                uint32_t ao = base + aOff + (uint32_t)mt * (16 * 80) + (uint32_t)k16 * 32;
                LDSM4(ah[mt], ao);
                LDSM4(al[mt], ao + 10240);
            }
#pragma unroll
            for (int ntp = 0; ntp < 4; ntp++) {
                uint32_t bh[4], bl[4];
                uint32_t bo = base + 20480 + bOff + (uint32_t)ntp * (16 * 80) + (uint32_t)k16 * 32;
                LDSM4(bh, bo);
                LDSM4(bl, bo + 10240);
#pragma unroll
                for (int mt = 0; mt < 2; mt++) {
#pragma unroll
                    for (int h8 = 0; h8 < 2; h8++) {
                        float* cc = acc[mt][ntp * 2 + h8];
                        mma16816(cc, ah[mt], bh + h8 * 2);
                        mma16816(cc, ah[mt], bl + h8 * 2);
                        mma16816(cc, al[mt], bh + h8 * 2);
                    }
                }
            }
        }
        __syncthreads();
    }

    // ---- epilogue ----
    float qs = (mode == 1 && z == 0) ? 0.125f : 1.0f;  // fold 1/sqrt(dk) into Q
#pragma unroll
    for (int mt = 0; mt < 2; mt++) {
#pragma unroll
        for (int nt8 = 0; nt8 < 8; nt8++) {
            const float* cc = acc[mt][nt8];
            int row = m0 + wm * 32 + mt * 16 + (lane >> 2);
            int col = n0 + wn * 64 + nt8 * 8 + (lane & 3) * 2;
            float bx = bias[col], by = bias[col + 1];
            float2 v0 = make_float2((cc[0] + bx) * qs, (cc[1] + by) * qs);
            float2 v1 = make_float2((cc[2] + bx) * qs, (cc[3] + by) * qs);
            if (mode == 1) {
                uint32_t* Ph = (z == 0) ? g_qh : (z == 1) ? g_kh : g_vh;
                uint32_t* Pl = (z == 0) ? g_ql : (z == 1) ? g_kl : g_vl;
                int h = col >> 6, d = col & 63;
                int bb = row >> 9, s = row & 511;
                size_t p0 = (((size_t)((bb * 16 + h) * 512 + s)) * 64 + d) >> 1;
                int bb2 = (row + 8) >> 9, s2 = (row + 8) & 511;
                size_t p1 = (((size_t)((bb2 * 16 + h) * 512 + s2)) * 64 + d) >> 1;
                uint32_t hi, lo;
                split2(v0.x, v0.y, hi, lo);
                Ph[p0] = hi; Pl[p0] = lo;
                split2(v1.x, v1.y, hi, lo);
                Ph[p1] = hi; Pl[p1] = lo;
            } else {
                *(float2*)&C0[(size_t)row * 1024 + col] = v0;
                *(float2*)&C0[(size_t)(row + 8) * 1024 + col] = v1;
            }
        }
    }
}

// ============ tensor-core flash attention with geometry bias ==================
static constexpr uint32_t ABUF = 36864;
static constexpr int ATTN_SMEM = 2 * 36864;   // 73728

__global__ __launch_bounds__(128) void attn_mma_kernel() {
    extern __shared__ __align__(16) char asmem[];
    uint32_t sbase = smem_u32(asmem);
    int tid = threadIdx.x, lane = tid & 31, w = tid >> 5;
    int q0 = blockIdx.x * 64, bh = blockIdx.y;
    size_t bhb = (size_t)bh * 65536;    // bytes per (b,h) slab: 512*64*2
    const char* pqh = (const char*)g_qh + bhb + (size_t)q0 * 128;
    const char* pql = (const char*)g_ql + bhb + (size_t)q0 * 128;
    const char* pkh = (const char*)g_kh + bhb;
    const char* pkl = (const char*)g_kl + bhb;
    const char* pvh = (const char*)g_vh + bhb;
    const char* pvl = (const char*)g_vl + bhb;
    const __half* lbp = g_logb + (size_t)bh * 262144;

    // stage Q into buf1 (hi @ +0, lo @ +9216)
#pragma unroll
    for (int p = 0; p < 4; p++) {
        int id = tid + p * 128, row = id >> 3, seg = id & 7;
        uint32_t d = sbase + ABUF + (uint32_t)row * 144 + (uint32_t)seg * 16;
        int so = row * 128 + seg * 16;
        CP_ASYNC16(d, pqh + so);
        CP_ASYNC16(d + 9216, pql + so);
    }
    CP_COMMIT();
    // chunk 0 into buf0
#pragma unroll
    for (int p = 0; p < 4; p++) {
        int id = tid + p * 128, row = id >> 3, seg = id & 7;
        uint32_t d = sbase + (uint32_t)row * 144 + (uint32_t)seg * 16;
        int so = row * 128 + seg * 16;
        CP_ASYNC16(d,         pkh + so);
        CP_ASYNC16(d + 9216,  pkl + so);
        CP_ASYNC16(d + 18432, pvh + so);
        CP_ASYNC16(d + 27648, pvl + so);
    }
    CP_COMMIT();
    CP_WAIT(1);               // Q staged
    __syncthreads();

    uint32_t qh[4][4], ql[4][4];
    {
        uint32_t aOff = (uint32_t)(w * 16 + (lane & 15)) * 144 + (uint32_t)(lane >> 4) * 16;
#pragma unroll
        for (int k16 = 0; k16 < 4; k16++) {
            LDSM4(qh[k16], sbase + ABUF + aOff + k16 * 32);
            LDSM4(ql[k16], sbase + ABUF + 9216 + aOff + k16 * 32);
        }
    }
    __syncthreads();          // Q region may now be overwritten (chunk1)

    float o[8][4];
#pragma unroll
    for (int t = 0; t < 8; t++)
#pragma unroll
        for (int q = 0; q < 4; q++) o[t][q] = 0.0f;
    float m0 = -1e30f, m1 = -1e30f, l0 = 0.0f, l1 = 0.0f;

    uint32_t bOffK = (uint32_t)((lane & 7) + ((lane >> 4) & 1) * 8) * 144
                   + (uint32_t)((lane >> 3) & 1) * 16;
    uint32_t vOff  = (uint32_t)((lane & 7) + ((lane >> 3) & 1) * 8) * 144
                   + (uint32_t)(lane >> 4) * 16;

    for (int c = 0; c < 8; c++) {
        if (c < 7) {
            int k0 = (c + 1) * 64;
            uint32_t bb = sbase + (uint32_t)((c + 1) & 1) * ABUF;
#pragma unroll
            for (int p = 0; p < 4; p++) {
                int id = tid + p * 128, row = id >> 3, seg = id & 7;
                uint32_t d = bb + (uint32_t)row * 144 + (uint32_t)seg * 16;
                int so = (k0 + row) * 128 + seg * 16;
                CP_ASYNC16(d,         pkh + so);
                CP_ASYNC16(d + 9216,  pkl + so);
                CP_ASYNC16(d + 18432, pvh + so);
                CP_ASYNC16(d + 27648, pvl + so);
            }
            CP_COMMIT();
            CP_WAIT(1);
        } else {
            CP_WAIT(0);
        }
        __syncthreads();
        uint32_t sb = sbase + (uint32_t)(c & 1) * ABUF;

        // prefetch logb tile (fp16)
        const __half* lp = lbp + (size_t)(q0 + w * 16 + (lane >> 2)) * 512
                         + c * 64 + (lane & 3) * 2;
        float2 lbA[8], lbB[8];
#pragma unroll
        for (int t = 0; t < 8; t++) {
            lbA[t] = __half22float2(*(const __half2*)(lp + t * 8));
            lbB[t] = __half22float2(*(const __half2*)(lp + 4096 + t * 8));
        }

        // S = Q K^T  (Q pre-scaled by 0.125)
        float s[8][4];
#pragma unroll
        for (int t = 0; t < 8; t++)
#pragma unroll
            for (int q = 0; q < 4; q++) s[t][q] = 0.0f;
#pragma unroll
        for (int k16 = 0; k16 < 4; k16++) {
#pragma unroll
            for (int ntp = 0; ntp < 4; ntp++) {
                uint32_t bh4[4], bl4[4];
                uint32_t bo = sb + bOffK + (uint32_t)ntp * 2304 + (uint32_t)k16 * 32;
                LDSM4(bh4, bo);
                LDSM4(bl4, bo + 9216);
#pragma unroll
                for (int h8 = 0; h8 < 2; h8++) {
                    float* cc = s[ntp * 2 + h8];
                    mma16816(cc, qh[k16], bh4 + h8 * 2);
                    mma16816(cc, ql[k16], bh4 + h8 * 2);
                    mma16816(cc, qh[k16], bl4 + h8 * 2);
                }
            }
        }

        // bias + online softmax
        float rm0 = -1e30f, rm1 = -1e30f;
#pragma unroll
        for (int t = 0; t < 8; t++) {
            s[t][0] += lbA[t].x; s[t][1] += lbA[t].y;
            s[t][2] += lbB[t].x; s[t][3] += lbB[t].y;
            rm0 = fmaxf(rm0, fmaxf(s[t][0], s[t][1]));
            rm1 = fmaxf(rm1, fmaxf(s[t][2], s[t][3]));
        }
        rm0 = fmaxf(rm0, __shfl_xor_sync(0xffffffffu, rm0, 1, 4));
        rm0 = fmaxf(rm0, __shfl_xor_sync(0xffffffffu, rm0, 2, 4));
        rm1 = fmaxf(rm1, __shfl_xor_sync(0xffffffffu, rm1, 1, 4));
        rm1 = fmaxf(rm1, __shfl_xor_sync(0xffffffffu, rm1, 2, 4));
        float mn0 = fmaxf(m0, rm0), mn1 = fmaxf(m1, rm1);
        float c0 = __expf(m0 - mn0), c1 = __expf(m1 - mn1);
        m0 = mn0; m1 = mn1;
        float ps0 = 0.0f, ps1 = 0.0f;
#pragma unroll
        for (int t = 0; t < 8; t++) {
            s[t][0] = __expf(s[t][0] - mn0); ps0 += s[t][0];
            s[t][1] = __expf(s[t][1] - mn0); ps0 += s[t][1];
            s[t][2] = __expf(s[t][2] - mn1); ps1 += s[t][2];
            s[t][3] = __expf(s[t][3] - mn1); ps1 += s[t][3];
        }
        ps0 += __shfl_xor_sync(0xffffffffu, ps0, 1, 4);
        ps0 += __shfl_xor_sync(0xffffffffu, ps0, 2, 4);
        ps1 += __shfl_xor_sync(0xffffffffu, ps1, 1, 4);
        ps1 += __shfl_xor_sync(0xffffffffu, ps1, 2, 4);
        l0 = l0 * c0 + ps0; l1 = l1 * c1 + ps1;
#pragma unroll
        for (int t = 0; t < 8; t++) {
            o[t][0] *= c0; o[t][1] *= c0; o[t][2] *= c1; o[t][3] *= c1;
        }

        // P accum -> A fragments (register repack), hi/lo split
        uint32_t ph[4][4], pl[4][4];
#pragma unroll
        for (int j = 0; j < 4; j++) {
            split2(s[2*j][0],   s[2*j][1],   ph[j][0], pl[j][0]);
            split2(s[2*j][2],   s[2*j][3],   ph[j][1], pl[j][1]);
            split2(s[2*j+1][0], s[2*j+1][1], ph[j][2], pl[j][2]);
            split2(s[2*j+1][2], s[2*j+1][3], ph[j][3], pl[j][3]);
        }

        // O += P V
#pragma unroll
        for (int j = 0; j < 4; j++) {
#pragma unroll
            for (int np = 0; np < 4; np++) {
                uint32_t vh4[4], vl4[4];
                uint32_t vo = sb + 18432 + vOff + (uint32_t)j * 2304 + (uint32_t)np * 32;
                LDSM4T(vh4, vo);
                LDSM4T(vl4, vo + 9216);
#pragma unroll
                for (int h8 = 0; h8 < 2; h8++) {
                    float* cc = o[np * 2 + h8];
                    mma16816(cc, ph[j], vh4 + h8 * 2);
                    mma16816(cc, pl[j], vh4 + h8 * 2);
                    mma16816(cc, ph[j], vl4 + h8 * 2);
                }
            }
        }
        __syncthreads();
    }

    // epilogue: normalize, write bf16 hi/lo directly for the output projection
    float i0 = 1.0f / l0, i1 = 1.0f / l1;
    int b = bh >> 4, hh = bh & 15;
    int r0 = q0 + w * 16 + (lane >> 2);
    size_t base0 = ((size_t)(b * 512 + r0) * 1024 + hh * 64 + (lane & 3) * 2) >> 1;
    size_t base1 = ((size_t)(b * 512 + r0 + 8) * 1024 + hh * 64 + (lane & 3) * 2) >> 1;
#pragma unroll
    for (int t = 0; t < 8; t++) {
        uint32_t hi, lo;
        split2(o[t][0] * i0, o[t][1] * i0, hi, lo);
        g_oh[base0 + t * 4] = hi; g_ol[base0 + t * 4] = lo;
        split2(o[t][2] * i1, o[t][3] * i1, hi, lo);
        g_oh[base1 + t * 4] = hi; g_ol[base1 + t * 4] = lo;
    }
}

// ---------------- launch ------------------------------------------------------
extern "C" void kernel_launch(void* const* d_in, const int* in_sizes, int n_in,
                              void* d_out, int out_size) {
    (void)in_sizes; (void)n_in; (void)out_size;
    const float* queries = (const float*)d_in[0];
    const float* keys    = (const float*)d_in[1];
    const float* values  = (const float*)d_in[2];
    const float* boxes   = (const float*)d_in[3];
    const float* Wq = (const float*)d_in[4];
    const float* bq = (const float*)d_in[5];
    const float* Wk = (const float*)d_in[6];
    const float* bk = (const float*)d_in[7];
    const float* Wv = (const float*)d_in[8];
    const float* bv = (const float*)d_in[9];
    const float* Wo = (const float*)d_in[10];
    const float* bo = (const float*)d_in[11];
    const float* Wg = (const float*)d_in[12];
    const float* bg = (const float*)d_in[13];
    float* out = (float*)d_out;

    cudaFuncSetAttribute(mma_gemm_kernel,
                         cudaFuncAttributeMaxDynamicSharedMemorySize, MG_SMEM);
    cudaFuncSetAttribute(attn_mma_kernel,
                         cudaFuncAttributeMaxDynamicSharedMemorySize, ATTN_SMEM);

    boxfeat_kernel<<<16, 256>>>(boxes);
    conv_kernel<<<4096, 256>>>(queries, 0);
    conv_kernel<<<4096, 256>>>(keys,    1);
    conv_kernel<<<4096, 256>>>(values,  2);
    conv_kernel<<<1024, 256>>>(Wq, 3);
    conv_kernel<<<1024, 256>>>(Wk, 4);
    conv_kernel<<<1024, 256>>>(Wv, 5);
    conv_kernel<<<1024, 256>>>(Wo, 6);
    bias_kernel<<<8192, 256>>>(Wg, bg);
    mma_gemm_kernel<<<dim3(32, 8, 3), 256, MG_SMEM>>>(
        bq, bk, bv, nullptr, /*a_sel=*/0, /*mode=*/1);
    attn_mma_kernel<<<dim3(8, 128), 128, ATTN_SMEM>>>();
    mma_gemm_kernel<<<dim3(32, 8, 1), 256, MG_SMEM>>>(
        bo, bo, bo, out, /*a_sel=*/1, /*mode=*/0);
}

// round 8
// speedup vs baseline: 2.4208x; 1.1195x over previous
#include <cuda_runtime.h>
#include <cuda_bf16.h>
#include <cuda_fp16.h>
#include <cstdint>

#define Bsz 8
#define Nsq 512
#define DM_ 1024
#define Hh 16
#define DK 64

// ---------------- scratch (static device arrays; no allocation) --------------
__device__ float g_logb[(size_t)Bsz*Hh*Nsq*Nsq]; // (b,h,n,m) fp32
__device__ float g_boxf[Bsz*Nsq*8];               // cx,cy,w,h,logw,logh
// packed bf16x2 hi/lo projections (b,h,n,d): idx = ((bh*512+n)*64+d)/2
__device__ uint32_t g_qh[Bsz*Hh*Nsq*DK/2];
__device__ uint32_t g_ql[Bsz*Hh*Nsq*DK/2];
__device__ uint32_t g_kh[Bsz*Hh*Nsq*DK/2];
__device__ uint32_t g_kl[Bsz*Hh*Nsq*DK/2];
__device__ uint32_t g_vh[Bsz*Hh*Nsq*DK/2];
__device__ uint32_t g_vl[Bsz*Hh*Nsq*DK/2];
// pre-converted GEMM operands (bf16 hi/lo pairs, row = 512 uint32)
__device__ uint32_t g_inh[3u*4096*512];   // queries/keys/values
__device__ uint32_t g_inl[3u*4096*512];
__device__ uint32_t g_wh[4u*1024*512];    // Wq,Wk,Wv,Wo
__device__ uint32_t g_wl[4u*1024*512];
__device__ uint32_t g_oh[4096u*512];      // attention output (b,n,h*64)
__device__ uint32_t g_ol[4096u*512];

// ---------------- helpers ----------------------------------------------------
__device__ __forceinline__ uint32_t smem_u32(const void* p) {
    uint32_t a;
    asm("{ .reg .u64 t; cvta.to.shared.u64 t, %1; cvt.u32.u64 %0, t; }" : "=r"(a) : "l"(p));
    return a;
}

#define LDSM4(r, a) \
    asm volatile("ldmatrix.sync.aligned.m8n8.x4.shared.b16 {%0,%1,%2,%3}, [%4];" \
        : "=r"((r)[0]), "=r"((r)[1]), "=r"((r)[2]), "=r"((r)[3]) : "r"(a))
#define LDSM4T(r, a) \
    asm volatile("ldmatrix.sync.aligned.m8n8.x4.trans.shared.b16 {%0,%1,%2,%3}, [%4];" \
        : "=r"((r)[0]), "=r"((r)[1]), "=r"((r)[2]), "=r"((r)[3]) : "r"(a))

#define CP_ASYNC16(dst, src) \
    asm volatile("cp.async.cg.shared.global [%0], [%1], 16;" :: "r"(dst), "l"(src) : "memory")
#define CP_COMMIT() asm volatile("cp.async.commit_group;" ::: "memory")
#define CP_WAIT(n)  asm volatile("cp.async.wait_group %0;" :: "n"(n) : "memory")

__device__ __forceinline__ void mma16816(float* c, const uint32_t* a, const uint32_t* b) {
    asm volatile("mma.sync.aligned.m16n8k16.row.col.f32.bf16.bf16.f32 "
        "{%0,%1,%2,%3}, {%4,%5,%6,%7}, {%8,%9}, {%0,%1,%2,%3};"
        : "+f"(c[0]), "+f"(c[1]), "+f"(c[2]), "+f"(c[3])
        : "r"(a[0]), "r"(a[1]), "r"(a[2]), "r"(a[3]), "r"(b[0]), "r"(b[1]));
}
__device__ __forceinline__ void mma16816h(float* c, const uint32_t* a, const uint32_t* b) {
    asm volatile("mma.sync.aligned.m16n8k16.row.col.f32.f16.f16.f32 "
        "{%0,%1,%2,%3}, {%4,%5,%6,%7}, {%8,%9}, {%0,%1,%2,%3};"
        : "+f"(c[0]), "+f"(c[1]), "+f"(c[2]), "+f"(c[3])
        : "r"(a[0]), "r"(a[1]), "r"(a[2]), "r"(a[3]), "r"(b[0]), "r"(b[1]));
}

// split two floats into packed bf16x2 hi + bf16x2 lo (residual)
__device__ __forceinline__ void split2(float x, float y, uint32_t& hi, uint32_t& lo) {
    asm("cvt.rn.bf16x2.f32 %0, %1, %2;" : "=r"(hi) : "f"(y), "f"(x));
    float fx = __uint_as_float(hi << 16);
    float fy = __uint_as_float(hi & 0xffff0000u);
    asm("cvt.rn.bf16x2.f32 %0, %1, %2;" : "=r"(lo) : "f"(y - fy), "f"(x - fx));
}
// fp16 variant
__device__ __forceinline__ void split2h(float x, float y, uint32_t& hi, uint32_t& lo) {
    __half2 h = __floats2half2_rn(x, y);
    hi = *reinterpret_cast<uint32_t*>(&h);
    float2 f = __half22float2(h);
    __half2 l = __floats2half2_rn(x - f.x, y - f.y);
    lo = *reinterpret_cast<uint32_t*>(&l);
}

// ---------------- box feature precompute ------------------------------------
__global__ void boxfeat_kernel(const float* __restrict__ boxes) {
    int i = blockIdx.x * 256 + threadIdx.x;            // < B*N = 4096
    float4 bx = *(const float4*)(boxes + (size_t)i * 4);
    float cx = (bx.x + bx.z) * 0.5f;
    float cy = (bx.y + bx.w) * 0.5f;
    float w  = (bx.z - bx.x) + 1.0f;
    float h  = (bx.w - bx.y) + 1.0f;
    float* o = g_boxf + (size_t)i * 8;
    o[0] = cx; o[1] = cy; o[2] = w; o[3] = h;
    o[4] = __logf(w); o[5] = __logf(h);
}

// ---------------- fused f32 -> bf16 hi/lo conversion (all 7 tensors) ----------
__global__ void conv_all_kernel(const float* __restrict__ q, const float* __restrict__ k,
                                const float* __restrict__ v, const float* __restrict__ wq,
                                const float* __restrict__ wk, const float* __restrict__ wv,
                                const float* __restrict__ wo) {
    size_t i = (size_t)blockIdx.x * 256 + threadIdx.x;   // < 4194304 float4s
    const float* src;
    uint32_t *dh, *dl;
    size_t off;
    if (i < 3145728) {
        int sel = (int)(i >> 20);
        off = i & 1048575;
        src = (sel == 0) ? q : (sel == 1) ? k : v;
        dh = g_inh + (size_t)sel * 2097152;
        dl = g_inl + (size_t)sel * 2097152;
    } else {
        size_t j = i - 3145728;
        int sel = (int)(j >> 18);
        off = j & 262143;
        src = (sel == 0) ? wq : (sel == 1) ? wk : (sel == 2) ? wv : wo;
        dh = g_wh + (size_t)sel * 524288;
        dl = g_wl + (size_t)sel * 524288;
    }
    float4 x = *(const float4*)(src + off * 4);
    uint32_t h0, l0, h1, l1;
    split2(x.x, x.y, h0, l0);
    split2(x.z, x.w, h1, l1);
    *(uint2*)(dh + off * 2) = make_uint2(h0, h1);
    *(uint2*)(dl + off * 2) = make_uint2(l0, l1);
}

// ---------------- geometry bias via fp16x2 HMMA ------------------------------
// Block 256 thr = 8 warps; block covers (b, n, m0..m0+255). Each thread computes
// emb(64) for one (n,m) pair -> smem fp16 hi/lo -> HMMA vs Wg -> log -> g_logb.
// smem: embh [256][144]@0, embl@36864, wgh [16][144]@73728, wgl@76032 -> 78336 B
static constexpr int BIAS_SMEM = 78336;

__global__ __launch_bounds__(256) void bias_mma_kernel(const float* __restrict__ Wg,
                                                       const float* __restrict__ bg) {
    extern __shared__ char bsm[];
    __shared__ float bgs[16];
    uint32_t sb = smem_u32(bsm);
    int tid = threadIdx.x, lane = tid & 31, w = tid >> 5;
    int blk = blockIdx.x;                 // 8192 blocks
    int m0 = (blk & 1) * 256;
    int n  = (blk >> 1) & 511;
    int b  = blk >> 10;
    int m  = m0 + tid;

    if (tid < 16) bgs[tid] = bg[tid];
    // stage Wg (16x64 f32) as fp16 hi/lo, 4 floats per thread
    {
        int row = tid >> 4, k4 = (tid & 15) * 4;
        float4 wv4 = *(const float4*)(Wg + row * 64 + k4);
        uint32_t h0, l0, h1, l1;
        split2h(wv4.x, wv4.y, h0, l0);
        split2h(wv4.z, wv4.w, h1, l1);
        *(uint2*)(bsm + 73728 + row * 144 + k4 * 2) = make_uint2(h0, h1);
        *(uint2*)(bsm + 76032 + row * 144 + k4 * 2) = make_uint2(l0, l1);
    }

    // pairwise geometry features
    const float* fn = g_boxf + (size_t)(b * 512 + n) * 8;
    const float* fm = g_boxf + (size_t)(b * 512 + m) * 8;
    float pos[4];
    pos[0] = __logf(fmaxf(fabsf(fn[0] - fm[0]) / fn[2], 1e-3f)) * 100.0f;
    pos[1] = __logf(fmaxf(fabsf(fn[1] - fm[1]) / fn[3], 1e-3f)) * 100.0f;
    pos[2] = (fn[4] - fm[4]) * 100.0f;
    pos[3] = (fn[5] - fm[5]) * 100.0f;

    const float DMAT[8] = {1.0f, 0.4216965034f, 0.1778279410f, 0.0749894209f,
                           0.0316227766f, 0.0133352143f, 0.0056234133f, 0.0023713737f};

    // emb row: k<32 -> sin(pos[k>>3]*DMAT[k&7]), k>=32 -> cos. fp16 hi/lo.
    uint32_t rowb = sb + (uint32_t)tid * 144;
#pragma unroll
    for (int d = 0; d < 4; d++) {
        float sv[8], cv[8];
#pragma unroll
        for (int j = 0; j < 8; j++) __sincosf(pos[d] * DMAT[j], &sv[j], &cv[j]);
        uint32_t sh[4], sl[4], ch[4], cl[4];
#pragma unroll
        for (int p = 0; p < 4; p++) {
            split2h(sv[2*p], sv[2*p+1], sh[p], sl[p]);
            split2h(cv[2*p], cv[2*p+1], ch[p], cl[p]);
        }
        // sin block -> 16B group d; cos block -> group 4+d
        *(uint4*)(bsm + (rowb - sb) + d * 16)        = make_uint4(sh[0], sh[1], sh[2], sh[3]);
        *(uint4*)(bsm + 36864 + (rowb - sb) + d * 16) = make_uint4(sl[0], sl[1], sl[2], sl[3]);
        *(uint4*)(bsm + (rowb - sb) + (4 + d) * 16)        = make_uint4(ch[0], ch[1], ch[2], ch[3]);
        *(uint4*)(bsm + 36864 + (rowb - sb) + (4 + d) * 16) = make_uint4(cl[0], cl[1], cl[2], cl[3]);
    }
    __syncthreads();

    // MMA: A = emb rows (warp-local 32 rows), B = Wg rows (16 heads)
    uint32_t aOff = sb + (uint32_t)(w * 32 + (lane & 15)) * 144 + (uint32_t)(lane >> 4) * 16;
    uint32_t bOff = sb + 73728 + (uint32_t)((lane & 7) + ((lane >> 4) & 1) * 8) * 144
                  + (uint32_t)((lane >> 3) & 1) * 16;
    float acc[2][2][4];
#pragma unroll
    for (int mt = 0; mt < 2; mt++)
#pragma unroll
        for (int n8 = 0; n8 < 2; n8++)
#pragma unroll
            for (int qq = 0; qq < 4; qq++) acc[mt][n8][qq] = 0.0f;

#pragma unroll
    for (int k16 = 0; k16 < 4; k16++) {
        uint32_t bh4[4], bl4[4];
        LDSM4(bh4, bOff + k16 * 32);
        LDSM4(bl4, bOff + 2304 + k16 * 32);
#pragma unroll
        for (int mt = 0; mt < 2; mt++) {
            uint32_t ah[4], al[4];
            LDSM4(ah, aOff + (uint32_t)mt * (16 * 144) + k16 * 32);
            LDSM4(al, aOff + 36864 + (uint32_t)mt * (16 * 144) + k16 * 32);
#pragma unroll
            for (int n8 = 0; n8 < 2; n8++) {
                float* cc = acc[mt][n8];
                mma16816h(cc, ah, bh4 + n8 * 2);
                mma16816h(cc, ah, bl4 + n8 * 2);
                mma16816h(cc, al, bh4 + n8 * 2);
            }
        }
    }

    // epilogue: g = relu+clip via fmax, log, scatter to [b][h][n][m]
    size_t nb = ((size_t)(b * 16) * 512 + n) * 512 + m0 + w * 32;
#pragma unroll
    for (int mt = 0; mt < 2; mt++) {
#pragma unroll
        for (int n8 = 0; n8 < 2; n8++) {
#pragma unroll
            for (int r2 = 0; r2 < 2; r2++) {
#pragma unroll
                for (int j = 0; j < 2; j++) {
                    int row = mt * 16 + (lane >> 2) + r2 * 8;
                    int col = n8 * 8 + (lane & 3) * 2 + j;
                    float g = acc[mt][n8][r2 * 2 + j] + bgs[col];
                    g = fmaxf(g, 1e-6f);
                    g_logb[nb + (size_t)col * 262144 + row] = __logf(g);
                }
            }
        }
    }
}

// ============ mma.sync GEMM on pre-converted bf16 hi/lo operands ==============
static constexpr int STAGE_B = 4 * 128 * 80;          // 40960
static constexpr int MG_SMEM = 2 * STAGE_B;           // 81920

__global__ __launch_bounds__(256, 2) void mma_gemm_kernel(
        const float* __restrict__ b0p, const float* __restrict__ b1p,
        const float* __restrict__ b2p, float* __restrict__ C0,
        int a_sel, int mode) {
    extern __shared__ char smem[];
    int z = blockIdx.z;
    const uint32_t* Ah;
    const uint32_t* Al;
    if (a_sel) { Ah = g_oh; Al = g_ol; }
    else       { Ah = g_inh + (size_t)z * 2097152; Al = g_inl + (size_t)z * 2097152; }
    int wsel = a_sel ? 3 : z;
    const uint32_t* Wh = g_wh + (size_t)wsel * 524288;
    const uint32_t* Wl = g_wl + (size_t)wsel * 524288;
    const float* bias = (z == 0) ? b0p : (z == 1) ? b1p : b2p;

    uint32_t sbase = smem_u32(smem);
    int tid = threadIdx.x;
    int lane = tid & 31, wid = tid >> 5;
    int wm = wid & 3, wn = wid >> 2;
    int m0 = blockIdx.x * 128, n0 = blockIdx.y * 128;

    const uint32_t* srcb[4];
    srcb[0] = Ah + (size_t)m0 * 512;
    srcb[1] = Al + (size_t)m0 * 512;
    srcb[2] = Wh + (size_t)n0 * 512;
    srcb[3] = Wl + (size_t)n0 * 512;

    uint32_t aOff = (uint32_t)(wm * 32 + (lane & 15)) * 80 + (uint32_t)(lane >> 4) * 16;
    uint32_t bOff = (uint32_t)(wn * 64 + (lane & 7) + ((lane >> 4) & 1) * 8) * 80
                  + (uint32_t)((lane >> 3) & 1) * 16;

    float acc[2][8][4];
#pragma unroll
    for (int i = 0; i < 2; i++)
#pragma unroll
        for (int j = 0; j < 8; j++)
#pragma unroll
            for (int q = 0; q < 4; q++) acc[i][j][q] = 0.0f;

    {
        uint32_t bb = sbase;
#pragma unroll
        for (int p = 0; p < 8; p++) {
            int mat = p >> 1;
            int id2 = tid + (p & 1) * 256;
            int row = id2 >> 2, seg = id2 & 3;
            uint32_t dst = bb + (uint32_t)mat * 10240 + (uint32_t)row * 80 + (uint32_t)seg * 16;
            CP_ASYNC16(dst, srcb[mat] + (size_t)row * 512 + seg * 4);
        }
        CP_COMMIT();
    }

    for (int c = 0; c < 32; ++c) {
        if (c + 1 < 32) {
            uint32_t bb = sbase + (uint32_t)((c + 1) & 1) * STAGE_B;
            int k0 = (c + 1) * 16;
#pragma unroll
            for (int p = 0; p < 8; p++) {
                int mat = p >> 1;
                int id2 = tid + (p & 1) * 256;
                int row = id2 >> 2, seg = id2 & 3;
                uint32_t dst = bb + (uint32_t)mat * 10240 + (uint32_t)row * 80 + (uint32_t)seg * 16;
                CP_ASYNC16(dst, srcb[mat] + (size_t)row * 512 + k0 + seg * 4);
            }
            CP_COMMIT();
            CP_WAIT(1);
        } else {
            CP_WAIT(0);
        }
        __syncthreads();

        uint32_t base = sbase + (uint32_t)(c & 1) * STAGE_B;
#pragma unroll
        for (int k16 = 0; k16 < 2; k16++) {
            uint32_t ah[2][4], al[2][4];
#pragma unroll
            for (int mt = 0; mt < 2; mt++) {
                uint32_t ao = base + aOff + (uint32_t)mt * (16 * 80) + (uint32_t)k16 * 32;
                LDSM4(ah[mt], ao);
                LDSM4(al[mt], ao + 10240);
            }
#pragma unroll
            for (int ntp = 0; ntp < 4; ntp++) {
                uint32_t bh[4], bl[4];
                uint32_t bo = base + 20480 + bOff + (uint32_t)ntp * (16 * 80) + (uint32_t)k16 * 32;
                LDSM4(bh, bo);
                LDSM4(bl, bo + 10240);
#pragma unroll
                for (int mt = 0; mt < 2; mt++) {
#pragma unroll
                    for (int h8 = 0; h8 < 2; h8++) {
                        float* cc = acc[mt][ntp * 2 + h8];
                        mma16816(cc, ah[mt], bh + h8 * 2);
                        mma16816(cc, ah[mt], bl + h8 * 2);
                        mma16816(cc, al[mt], bh + h8 * 2);
                    }
                }
            }
        }
        __syncthreads();
    }

    float qs = (mode == 1 && z == 0) ? 0.125f : 1.0f;
#pragma unroll
    for (int mt = 0; mt < 2; mt++) {
#pragma unroll
        for (int nt8 = 0; nt8 < 8; nt8++) {
            const float* cc = acc[mt][nt8];
            int row = m0 + wm * 32 + mt * 16 + (lane >> 2);
            int col = n0 + wn * 64 + nt8 * 8 + (lane & 3) * 2;
            float bx = bias[col], by = bias[col + 1];
            float2 v0 = make_float2((cc[0] + bx) * qs, (cc[1] + by) * qs);
            float2 v1 = make_float2((cc[2] + bx) * qs, (cc[3] + by) * qs);
            if (mode == 1) {
                uint32_t* Ph = (z == 0) ? g_qh : (z == 1) ? g_kh : g_vh;
                uint32_t* Pl = (z == 0) ? g_ql : (z == 1) ? g_kl : g_vl;
                int h = col >> 6, d = col & 63;
                int bb = row >> 9, s = row & 511;
                size_t p0 = (((size_t)((bb * 16 + h) * 512 + s)) * 64 + d) >> 1;
                int bb2 = (row + 8) >> 9, s2 = (row + 8) & 511;
                size_t p1 = (((size_t)((bb2 * 16 + h) * 512 + s2)) * 64 + d) >> 1;
                uint32_t hi, lo;
                split2(v0.x, v0.y, hi, lo);
                Ph[p0] = hi; Pl[p0] = lo;
                split2(v1.x, v1.y, hi, lo);
                Ph[p1] = hi; Pl[p1] = lo;
            } else {
                *(float2*)&C0[(size_t)row * 1024 + col] = v0;
                *(float2*)&C0[(size_t)(row + 8) * 1024 + col] = v1;
            }
        }
    }
}

// ============ tensor-core flash attention with geometry bias ==================
static constexpr uint32_t ABUF = 36864;
static constexpr int ATTN_SMEM = 2 * 36864;   // 73728

__global__ __launch_bounds__(128) void attn_mma_kernel() {
    extern __shared__ __align__(16) char asmem[];
    uint32_t sbase = smem_u32(asmem);
    int tid = threadIdx.x, lane = tid & 31, w = tid >> 5;
    int q0 = blockIdx.x * 64, bh = blockIdx.y;
    size_t bhb = (size_t)bh * 65536;
    const char* pqh = (const char*)g_qh + bhb + (size_t)q0 * 128;
    const char* pql = (const char*)g_ql + bhb + (size_t)q0 * 128;
    const char* pkh = (const char*)g_kh + bhb;
    const char* pkl = (const char*)g_kl + bhb;
    const char* pvh = (const char*)g_vh + bhb;
    const char* pvl = (const char*)g_vl + bhb;
    const float* lbp = g_logb + (size_t)bh * 262144;

#pragma unroll
    for (int p = 0; p < 4; p++) {
        int id = tid + p * 128, row = id >> 3, seg = id & 7;
        uint32_t d = sbase + ABUF + (uint32_t)row * 144 + (uint32_t)seg * 16;
        int so = row * 128 + seg * 16;
        CP_ASYNC16(d, pqh + so);
        CP_ASYNC16(d + 9216, pql + so);
    }
    CP_COMMIT();
#pragma unroll
    for (int p = 0; p < 4; p++) {
        int id = tid + p * 128, row = id >> 3, seg = id & 7;
        uint32_t d = sbase + (uint32_t)row * 144 + (uint32_t)seg * 16;
        int so = row * 128 + seg * 16;
        CP_ASYNC16(d,         pkh + so);
        CP_ASYNC16(d + 9216,  pkl + so);
        CP_ASYNC16(d + 18432, pvh + so);
        CP_ASYNC16(d + 27648, pvl + so);
    }
    CP_COMMIT();
    CP_WAIT(1);
    __syncthreads();

    uint32_t qh[4][4], ql[4][4];
    {
        uint32_t aOff = (uint32_t)(w * 16 + (lane & 15)) * 144 + (uint32_t)(lane >> 4) * 16;
#pragma unroll
        for (int k16 = 0; k16 < 4; k16++) {
            LDSM4(qh[k16], sbase + ABUF + aOff + k16 * 32);
            LDSM4(ql[k16], sbase + ABUF + 9216 + aOff + k16 * 32);
        }
    }
    __syncthreads();

    float o[8][4];
#pragma unroll
    for (int t = 0; t < 8; t++)
#pragma unroll
        for (int q = 0; q < 4; q++) o[t][q] = 0.0f;
    float m0 = -1e30f, m1 = -1e30f, l0 = 0.0f, l1 = 0.0f;

    uint32_t bOffK = (uint32_t)((lane & 7) + ((lane >> 4) & 1) * 8) * 144
                   + (uint32_t)((lane >> 3) & 1) * 16;
    uint32_t vOff  = (uint32_t)((lane & 7) + ((lane >> 3) & 1) * 8) * 144
                   + (uint32_t)(lane >> 4) * 16;

    for (int c = 0; c < 8; c++) {
        if (c < 7) {
            int k0 = (c + 1) * 64;
            uint32_t bb = sbase + (uint32_t)((c + 1) & 1) * ABUF;
#pragma unroll
            for (int p = 0; p < 4; p++) {
                int id = tid + p * 128, row = id >> 3, seg = id & 7;
                uint32_t d = bb + (uint32_t)row * 144 + (uint32_t)seg * 16;
                int so = (k0 + row) * 128 + seg * 16;
                CP_ASYNC16(d,         pkh + so);
                CP_ASYNC16(d + 9216,  pkl + so);
                CP_ASYNC16(d + 18432, pvh + so);
                CP_ASYNC16(d + 27648, pvl + so);
            }
            CP_COMMIT();
            CP_WAIT(1);
        } else {
            CP_WAIT(0);
        }
        __syncthreads();
        uint32_t sb = sbase + (uint32_t)(c & 1) * ABUF;

        const float* lp = lbp + (size_t)(q0 + w * 16 + (lane >> 2)) * 512
                        + c * 64 + (lane & 3) * 2;
        float2 lbA[8], lbB[8];
#pragma unroll
        for (int t = 0; t < 8; t++) {
            lbA[t] = *(const float2*)(lp + t * 8);
            lbB[t] = *(const float2*)(lp + 4096 + t * 8);
        }

        float s[8][4];
#pragma unroll
        for (int t = 0; t < 8; t++)
#pragma unroll
            for (int q = 0; q < 4; q++) s[t][q] = 0.0f;
#pragma unroll
        for (int k16 = 0; k16 < 4; k16++) {
#pragma unroll
            for (int ntp = 0; ntp < 4; ntp++) {
                uint32_t bh4[4], bl4[4];
                uint32_t bo = sb + bOffK + (uint32_t)ntp * 2304 + (uint32_t)k16 * 32;
                LDSM4(bh4, bo);
                LDSM4(bl4, bo + 9216);
#pragma unroll
                for (int h8 = 0; h8 < 2; h8++) {
                    float* cc = s[ntp * 2 + h8];
                    mma16816(cc, qh[k16], bh4 + h8 * 2);
                    mma16816(cc, ql[k16], bh4 + h8 * 2);
                    mma16816(cc, qh[k16], bl4 + h8 * 2);
                }
            }
        }

        float rm0 = -1e30f, rm1 = -1e30f;
#pragma unroll
        for (int t = 0; t < 8; t++) {
            s[t][0] += lbA[t].x; s[t][1] += lbA[t].y;
            s[t][2] += lbB[t].x; s[t][3] += lbB[t].y;
            rm0 = fmaxf(rm0, fmaxf(s[t][0], s[t][1]));
            rm1 = fmaxf(rm1, fmaxf(s[t][2], s[t][3]));
        }
        rm0 = fmaxf(rm0, __shfl_xor_sync(0xffffffffu, rm0, 1, 4));
        rm0 = fmaxf(rm0, __shfl_xor_sync(0xffffffffu, rm0, 2, 4));
        rm1 = fmaxf(rm1, __shfl_xor_sync(0xffffffffu, rm1, 1, 4));
        rm1 = fmaxf(rm1, __shfl_xor_sync(0xffffffffu, rm1, 2, 4));
        float mn0 = fmaxf(m0, rm0), mn1 = fmaxf(m1, rm1);
        float c0 = __expf(m0 - mn0), c1 = __expf(m1 - mn1);
        m0 = mn0; m1 = mn1;
        float ps0 = 0.0f, ps1 = 0.0f;
#pragma unroll
        for (int t = 0; t < 8; t++) {
            s[t][0] = __expf(s[t][0] - mn0); ps0 += s[t][0];
            s[t][1] = __expf(s[t][1] - mn0); ps0 += s[t][1];
            s[t][2] = __expf(s[t][2] - mn1); ps1 += s[t][2];
            s[t][3] = __expf(s[t][3] - mn1); ps1 += s[t][3];
        }
        ps0 += __shfl_xor_sync(0xffffffffu, ps0, 1, 4);
        ps0 += __shfl_xor_sync(0xffffffffu, ps0, 2, 4);
        ps1 += __shfl_xor_sync(0xffffffffu, ps1, 1, 4);
        ps1 += __shfl_xor_sync(0xffffffffu, ps1, 2, 4);
        l0 = l0 * c0 + ps0; l1 = l1 * c1 + ps1;
#pragma unroll
        for (int t = 0; t < 8; t++) {
            o[t][0] *= c0; o[t][1] *= c0; o[t][2] *= c1; o[t][3] *= c1;
        }

        uint32_t ph[4][4], pl[4][4];
#pragma unroll
        for (int j = 0; j < 4; j++) {
            split2(s[2*j][0],   s[2*j][1],   ph[j][0], pl[j][0]);
            split2(s[2*j][2],   s[2*j][3],   ph[j][1], pl[j][1]);
            split2(s[2*j+1][0], s[2*j+1][1], ph[j][2], pl[j][2]);
            split2(s[2*j+1][2], s[2*j+1][3], ph[j][3], pl[j][3]);
        }

#pragma unroll
        for (int j = 0; j < 4; j++) {
#pragma unroll
            for (int np = 0; np < 4; np++) {
                uint32_t vh4[4], vl4[4];
                uint32_t vo = sb + 18432 + vOff + (uint32_t)j * 2304 + (uint32_t)np * 32;
                LDSM4T(vh4, vo);
                LDSM4T(vl4, vo + 9216);
#pragma unroll
                for (int h8 = 0; h8 < 2; h8++) {
                    float* cc = o[np * 2 + h8];
                    mma16816(cc, ph[j], vh4 + h8 * 2);
                    mma16816(cc, pl[j], vh4 + h8 * 2);
                    mma16816(cc, ph[j], vl4 + h8 * 2);
                }
            }
        }
        __syncthreads();
    }

    float i0 = 1.0f / l0, i1 = 1.0f / l1;
    int b = bh >> 4, hh = bh & 15;
    int r0 = q0 + w * 16 + (lane >> 2);
    size_t base0 = ((size_t)(b * 512 + r0) * 1024 + hh * 64 + (lane & 3) * 2) >> 1;
    size_t base1 = ((size_t)(b * 512 + r0 + 8) * 1024 + hh * 64 + (lane & 3) * 2) >> 1;
#pragma unroll
    for (int t = 0; t < 8; t++) {
        uint32_t hi, lo;
        split2(o[t][0] * i0, o[t][1] * i0, hi, lo);
        g_oh[base0 + t * 4] = hi; g_ol[base0 + t * 4] = lo;
        split2(o[t][2] * i1, o[t][3] * i1, hi, lo);
        g_oh[base1 + t * 4] = hi; g_ol[base1 + t * 4] = lo;
    }
}

// ---------------- launch ------------------------------------------------------
extern "C" void kernel_launch(void* const* d_in, const int* in_sizes, int n_in,
                              void* d_out, int out_size) {
    (void)in_sizes; (void)n_in; (void)out_size;
    const float* queries = (const float*)d_in[0];
    const float* keys    = (const float*)d_in[1];
    const float* values  = (const float*)d_in[2];
    const float* boxes   = (const float*)d_in[3];
    const float* bq = (const float*)d_in[5];
    const float* bk = (const float*)d_in[7];
    const float* bv = (const float*)d_in[9];
    const float* bo = (const float*)d_in[11];
    const float* Wq = (const float*)d_in[4];
    const float* Wk = (const float*)d_in[6];
    const float* Wv = (const float*)d_in[8];
    const float* Wo = (const float*)d_in[10];
    const float* Wg = (const float*)d_in[12];
    const float* bg = (const float*)d_in[13];
    float* out = (float*)d_out;

    cudaFuncSetAttribute(mma_gemm_kernel,
                         cudaFuncAttributeMaxDynamicSharedMemorySize, MG_SMEM);
    cudaFuncSetAttribute(attn_mma_kernel,
                         cudaFuncAttributeMaxDynamicSharedMemorySize, ATTN_SMEM);
    cudaFuncSetAttribute(bias_mma_kernel,
                         cudaFuncAttributeMaxDynamicSharedMemorySize, BIAS_SMEM);

    boxfeat_kernel<<<16, 256>>>(boxes);
    conv_all_kernel<<<16384, 256>>>(queries, keys, values, Wq, Wk, Wv, Wo);
    bias_mma_kernel<<<8192, 256, BIAS_SMEM>>>(Wg, bg);
    mma_gemm_kernel<<<dim3(32, 8, 3), 256, MG_SMEM>>>(
        bq, bk, bv, nullptr, /*a_sel=*/0, /*mode=*/1);
    attn_mma_kernel<<<dim3(8, 128), 128, ATTN_SMEM>>>();
    mma_gemm_kernel<<<dim3(32, 8, 1), 256, MG_SMEM>>>(
        bo, bo, bo, out, /*a_sel=*/1, /*mode=*/0);
}

// round 11
// speedup vs baseline: 2.5919x; 1.0707x over previous
#include <cuda_runtime.h>
#include <cuda_bf16.h>
#include <cuda_fp16.h>
#include <cstdint>

#define Bsz 8
#define Nsq 512
#define DM_ 1024
#define Hh 16
#define DK 64

// ---------------- scratch (static device arrays; no allocation) --------------
__device__ float g_logb[(size_t)Bsz*Hh*Nsq*Nsq]; // (b,h,n,m) fp32
__device__ float g_boxf[Bsz*Nsq*8];               // cx,cy,w,h,logw,logh
// packed bf16x2 hi/lo projections (b,h,n,d): idx = ((bh*512+n)*64+d)/2
__device__ uint32_t g_qh[Bsz*Hh*Nsq*DK/2];
__device__ uint32_t g_ql[Bsz*Hh*Nsq*DK/2];
__device__ uint32_t g_kh[Bsz*Hh*Nsq*DK/2];
__device__ uint32_t g_kl[Bsz*Hh*Nsq*DK/2];
__device__ uint32_t g_vh[Bsz*Hh*Nsq*DK/2];
__device__ uint32_t g_vl[Bsz*Hh*Nsq*DK/2];
// pre-converted GEMM operands (bf16 hi/lo pairs, row = 512 uint32)
__device__ uint32_t g_inh[3u*4096*512];   // queries/keys/values
__device__ uint32_t g_inl[3u*4096*512];
__device__ uint32_t g_wh[4u*1024*512];    // Wq,Wk,Wv,Wo
__device__ uint32_t g_wl[4u*1024*512];
__device__ uint32_t g_oh[4096u*512];      // attention output (b,n,h*64)
__device__ uint32_t g_ol[4096u*512];

// ---------------- helpers ----------------------------------------------------
__device__ __forceinline__ uint32_t smem_u32(const void* p) {
    uint32_t a;
    asm("{ .reg .u64 t; cvta.to.shared.u64 t, %1; cvt.u32.u64 %0, t; }" : "=r"(a) : "l"(p));
    return a;
}

#define LDSM4(r, a) \
    asm volatile("ldmatrix.sync.aligned.m8n8.x4.shared.b16 {%0,%1,%2,%3}, [%4];" \
        : "=r"((r)[0]), "=r"((r)[1]), "=r"((r)[2]), "=r"((r)[3]) : "r"(a))
#define LDSM4T(r, a) \
    asm volatile("ldmatrix.sync.aligned.m8n8.x4.trans.shared.b16 {%0,%1,%2,%3}, [%4];" \
        : "=r"((r)[0]), "=r"((r)[1]), "=r"((r)[2]), "=r"((r)[3]) : "r"(a))

#define CP_ASYNC16(dst, src) \
    asm volatile("cp.async.cg.shared.global [%0], [%1], 16;" :: "r"(dst), "l"(src) : "memory")
#define CP_COMMIT() asm volatile("cp.async.commit_group;" ::: "memory")
#define CP_WAIT(n)  asm volatile("cp.async.wait_group %0;" :: "n"(n) : "memory")

__device__ __forceinline__ void mma16816(float* c, const uint32_t* a, const uint32_t* b) {
    asm volatile("mma.sync.aligned.m16n8k16.row.col.f32.bf16.bf16.f32 "
        "{%0,%1,%2,%3}, {%4,%5,%6,%7}, {%8,%9}, {%0,%1,%2,%3};"
        : "+f"(c[0]), "+f"(c[1]), "+f"(c[2]), "+f"(c[3])
        : "r"(a[0]), "r"(a[1]), "r"(a[2]), "r"(a[3]), "r"(b[0]), "r"(b[1]));
}
__device__ __forceinline__ void mma16816h(float* c, const uint32_t* a, const uint32_t* b) {
    asm volatile("mma.sync.aligned.m16n8k16.row.col.f32.f16.f16.f32 "
        "{%0,%1,%2,%3}, {%4,%5,%6,%7}, {%8,%9}, {%0,%1,%2,%3};"
        : "+f"(c[0]), "+f"(c[1]), "+f"(c[2]), "+f"(c[3])
        : "r"(a[0]), "r"(a[1]), "r"(a[2]), "r"(a[3]), "r"(b[0]), "r"(b[1]));
}

// split two floats into packed bf16x2 hi + bf16x2 lo (residual)
__device__ __forceinline__ void split2(float x, float y, uint32_t& hi, uint32_t& lo) {
    asm("cvt.rn.bf16x2.f32 %0, %1, %2;" : "=r"(hi) : "f"(y), "f"(x));
    float fx = __uint_as_float(hi << 16);
    float fy = __uint_as_float(hi & 0xffff0000u);
    asm("cvt.rn.bf16x2.f32 %0, %1, %2;" : "=r"(lo) : "f"(y - fy), "f"(x - fx));
}
// fp16 variant
__device__ __forceinline__ void split2h(float x, float y, uint32_t& hi, uint32_t& lo) {
    __half2 h = __floats2half2_rn(x, y);
    hi = *reinterpret_cast<uint32_t*>(&h);
    float2 f = __half22float2(h);
    __half2 l = __floats2half2_rn(x - f.x, y - f.y);
    lo = *reinterpret_cast<uint32_t*>(&l);
}

// ---------------- box feature precompute ------------------------------------
__global__ void boxfeat_kernel(const float* __restrict__ boxes) {
    int i = blockIdx.x * 256 + threadIdx.x;            // < B*N = 4096
    float4 bx = *(const float4*)(boxes + (size_t)i * 4);
    float cx = (bx.x + bx.z) * 0.5f;
    float cy = (bx.y + bx.w) * 0.5f;
    float w  = (bx.z - bx.x) + 1.0f;
    float h  = (bx.w - bx.y) + 1.0f;
    float* o = g_boxf + (size_t)i * 8;
    o[0] = cx; o[1] = cy; o[2] = w; o[3] = h;
    o[4] = __logf(w); o[5] = __logf(h);
}

// ---------------- fused f32 -> bf16 hi/lo conversion (all 7 tensors) ----------
__global__ void conv_all_kernel(const float* __restrict__ q, const float* __restrict__ k,
                                const float* __restrict__ v, const float* __restrict__ wq,
                                const float* __restrict__ wk, const float* __restrict__ wv,
                                const float* __restrict__ wo) {
    size_t i = (size_t)blockIdx.x * 256 + threadIdx.x;   // < 4194304 float4s
    const float* src;
    uint32_t *dh, *dl;
    size_t off;
    if (i < 3145728) {
        int sel = (int)(i >> 20);
        off = i & 1048575;
        src = (sel == 0) ? q : (sel == 1) ? k : v;
        dh = g_inh + (size_t)sel * 2097152;
        dl = g_inl + (size_t)sel * 2097152;
    } else {
        size_t j = i - 3145728;
        int sel = (int)(j >> 18);
        off = j & 262143;
        src = (sel == 0) ? wq : (sel == 1) ? wk : (sel == 2) ? wv : wo;
        dh = g_wh + (size_t)sel * 524288;
        dl = g_wl + (size_t)sel * 524288;
    }
    float4 x = *(const float4*)(src + off * 4);
    uint32_t h0, l0, h1, l1;
    split2(x.x, x.y, h0, l0);
    split2(x.z, x.w, h1, l1);
    *(uint2*)(dh + off * 2) = make_uint2(h0, h1);
    *(uint2*)(dl + off * 2) = make_uint2(l0, l1);
}

// ---------------- geometry bias via fp16x2 HMMA ------------------------------
static constexpr int BIAS_SMEM = 78336;

__global__ __launch_bounds__(256) void bias_mma_kernel(const float* __restrict__ Wg,
                                                       const float* __restrict__ bg) {
    extern __shared__ char bsm[];
    __shared__ float bgs[16];
    uint32_t sb = smem_u32(bsm);
    int tid = threadIdx.x, lane = tid & 31, w = tid >> 5;
    int blk = blockIdx.x;                 // 8192 blocks
    int m0 = (blk & 1) * 256;
    int n  = (blk >> 1) & 511;
    int b  = blk >> 10;
    int m  = m0 + tid;

    if (tid < 16) bgs[tid] = bg[tid];
    {
        int row = tid >> 4, k4 = (tid & 15) * 4;
        float4 wv4 = *(const float4*)(Wg + row * 64 + k4);
        uint32_t h0, l0, h1, l1;
        split2h(wv4.x, wv4.y, h0, l0);
        split2h(wv4.z, wv4.w, h1, l1);
        *(uint2*)(bsm + 73728 + row * 144 + k4 * 2) = make_uint2(h0, h1);
        *(uint2*)(bsm + 76032 + row * 144 + k4 * 2) = make_uint2(l0, l1);
    }

    const float* fn = g_boxf + (size_t)(b * 512 + n) * 8;
    const float* fm = g_boxf + (size_t)(b * 512 + m) * 8;
    float pos[4];
    pos[0] = __logf(fmaxf(fabsf(fn[0] - fm[0]) / fn[2], 1e-3f)) * 100.0f;
    pos[1] = __logf(fmaxf(fabsf(fn[1] - fm[1]) / fn[3], 1e-3f)) * 100.0f;
    pos[2] = (fn[4] - fm[4]) * 100.0f;
    pos[3] = (fn[5] - fm[5]) * 100.0f;

    const float DMAT[8] = {1.0f, 0.4216965034f, 0.1778279410f, 0.0749894209f,
                           0.0316227766f, 0.0133352143f, 0.0056234133f, 0.0023713737f};

    uint32_t rowb = sb + (uint32_t)tid * 144;
#pragma unroll
    for (int d = 0; d < 4; d++) {
        float sv[8], cv[8];
#pragma unroll
        for (int j = 0; j < 8; j++) __sincosf(pos[d] * DMAT[j], &sv[j], &cv[j]);
        uint32_t sh[4], sl[4], ch[4], cl[4];
#pragma unroll
        for (int p = 0; p < 4; p++) {
            split2h(sv[2*p], sv[2*p+1], sh[p], sl[p]);
            split2h(cv[2*p], cv[2*p+1], ch[p], cl[p]);
        }
        *(uint4*)(bsm + (rowb - sb) + d * 16)        = make_uint4(sh[0], sh[1], sh[2], sh[3]);
        *(uint4*)(bsm + 36864 + (rowb - sb) + d * 16) = make_uint4(sl[0], sl[1], sl[2], sl[3]);
        *(uint4*)(bsm + (rowb - sb) + (4 + d) * 16)        = make_uint4(ch[0], ch[1], ch[2], ch[3]);
        *(uint4*)(bsm + 36864 + (rowb - sb) + (4 + d) * 16) = make_uint4(cl[0], cl[1], cl[2], cl[3]);
    }
    __syncthreads();

    uint32_t aOff = sb + (uint32_t)(w * 32 + (lane & 15)) * 144 + (uint32_t)(lane >> 4) * 16;
    uint32_t bOff = sb + 73728 + (uint32_t)((lane & 7) + ((lane >> 4) & 1) * 8) * 144
                  + (uint32_t)((lane >> 3) & 1) * 16;
    float acc[2][2][4];
#pragma unroll
    for (int mt = 0; mt < 2; mt++)
#pragma unroll
        for (int n8 = 0; n8 < 2; n8++)
#pragma unroll
            for (int qq = 0; qq < 4; qq++) acc[mt][n8][qq] = 0.0f;

#pragma unroll
    for (int k16 = 0; k16 < 4; k16++) {
        uint32_t bh4[4], bl4[4];
        LDSM4(bh4, bOff + k16 * 32);
        LDSM4(bl4, bOff + 2304 + k16 * 32);
#pragma unroll
        for (int mt = 0; mt < 2; mt++) {
            uint32_t ah[4], al[4];
            LDSM4(ah, aOff + (uint32_t)mt * (16 * 144) + k16 * 32);
            LDSM4(al, aOff + 36864 + (uint32_t)mt * (16 * 144) + k16 * 32);
#pragma unroll
            for (int n8 = 0; n8 < 2; n8++) {
                float* cc = acc[mt][n8];
                mma16816h(cc, ah, bh4 + n8 * 2);
                mma16816h(cc, ah, bl4 + n8 * 2);
                mma16816h(cc, al, bh4 + n8 * 2);
            }
        }
    }

    size_t nb = ((size_t)(b * 16) * 512 + n) * 512 + m0 + w * 32;
#pragma unroll
    for (int mt = 0; mt < 2; mt++) {
#pragma unroll
        for (int n8 = 0; n8 < 2; n8++) {
#pragma unroll
            for (int r2 = 0; r2 < 2; r2++) {
#pragma unroll
                for (int j = 0; j < 2; j++) {
                    int row = mt * 16 + (lane >> 2) + r2 * 8;
                    int col = n8 * 8 + (lane & 3) * 2 + j;
                    float g = acc[mt][n8][r2 * 2 + j] + bgs[col];
                    g = fmaxf(g, 1e-6f);
                    g_logb[nb + (size_t)col * 262144 + row] = __logf(g);
                }
            }
        }
    }
}

// ============ mma.sync GEMM, 3-stage cp.async ring, swizzled 64B rows =========
// Per-stage layout: Ah@0, Al@8192, Bh@16384, Bl@24576 (each 128 rows x 64B).
// Swizzle: 16B seg s of row r lives at phys seg s ^ ((r>>1)&3).
static constexpr int STAGE_B = 4 * 128 * 64;          // 32768
static constexpr int MG_SMEM = 3 * STAGE_B;           // 98304

__global__ __launch_bounds__(256, 2) void mma_gemm_kernel(
        const float* __restrict__ b0p, const float* __restrict__ b1p,
        const float* __restrict__ b2p, float* __restrict__ C0,
        int a_sel, int mode) {
    extern __shared__ char smem[];
    int z = blockIdx.z;
    const uint32_t* Ah;
    const uint32_t* Al;
    if (a_sel) { Ah = g_oh; Al = g_ol; }
    else       { Ah = g_inh + (size_t)z * 2097152; Al = g_inl + (size_t)z * 2097152; }
    int wsel = a_sel ? 3 : z;
    const uint32_t* Wh = g_wh + (size_t)wsel * 524288;
    const uint32_t* Wl = g_wl + (size_t)wsel * 524288;
    const float* bias = (z == 0) ? b0p : (z == 1) ? b1p : b2p;

    uint32_t sbase = smem_u32(smem);
    int tid = threadIdx.x;
    int lane = tid & 31, wid = tid >> 5;
    int wm = wid & 3, wn = wid >> 2;
    int m0 = blockIdx.x * 128, n0 = blockIdx.y * 128;

    const uint32_t* srcb[4];
    srcb[0] = Ah + (size_t)m0 * 512;
    srcb[1] = Al + (size_t)m0 * 512;
    srcb[2] = Wh + (size_t)n0 * 512;
    srcb[3] = Wl + (size_t)n0 * 512;

    int arow0 = wm * 32 + (lane & 15);
    uint32_t ahalf = (uint32_t)(lane >> 4);
    int brow0 = wn * 64 + (lane & 7) + ((lane >> 4) & 1) * 8;
    uint32_t bhalf = (uint32_t)((lane >> 3) & 1);

    float acc[2][8][4];
#pragma unroll
    for (int i = 0; i < 2; i++)
#pragma unroll
        for (int j = 0; j < 8; j++)
#pragma unroll
            for (int q = 0; q < 4; q++) acc[i][j][q] = 0.0f;

    // prologue: chunks 0 and 1
#pragma unroll
    for (int pc = 0; pc < 2; pc++) {
        uint32_t bb = sbase + (uint32_t)pc * STAGE_B;
        int k0 = pc * 16;
#pragma unroll
        for (int p = 0; p < 8; p++) {
            int mat = p >> 1;
            int id2 = tid + (p & 1) * 256;
            int row = id2 >> 2, seg = id2 & 3;
            uint32_t dst = bb + (uint32_t)mat * 8192 + (uint32_t)row * 64
                         + (uint32_t)((seg ^ ((row >> 1) & 3)) * 16);
            CP_ASYNC16(dst, srcb[mat] + (size_t)row * 512 + k0 + seg * 4);
        }
        CP_COMMIT();
    }

    for (int c = 0; c < 32; ++c) {
        if (c < 31) { CP_WAIT(1); } else { CP_WAIT(0); }
        __syncthreads();

        if (c + 2 < 32) {
            uint32_t bb = sbase + (uint32_t)((c + 2) % 3) * STAGE_B;
            int k0 = (c + 2) * 16;
#pragma unroll
            for (int p = 0; p < 8; p++) {
                int mat = p >> 1;
                int id2 = tid + (p & 1) * 256;
                int row = id2 >> 2, seg = id2 & 3;
                uint32_t dst = bb + (uint32_t)mat * 8192 + (uint32_t)row * 64
                             + (uint32_t)((seg ^ ((row >> 1) & 3)) * 16);
                CP_ASYNC16(dst, srcb[mat] + (size_t)row * 512 + k0 + seg * 4);
            }
            CP_COMMIT();
        }

        uint32_t base = sbase + (uint32_t)(c % 3) * STAGE_B;
#pragma unroll
        for (int k16 = 0; k16 < 2; k16++) {
            uint32_t ah[2][4], al[2][4];
#pragma unroll
            for (int mt = 0; mt < 2; mt++) {
                int ar = arow0 + mt * 16;
                uint32_t aseg = ((uint32_t)(k16 * 2) + ahalf) ^ ((uint32_t)(ar >> 1) & 3u);
                uint32_t ao = base + (uint32_t)ar * 64 + aseg * 16;
                LDSM4(ah[mt], ao);
                LDSM4(al[mt], ao + 8192);
            }
#pragma unroll
            for (int ntp = 0; ntp < 4; ntp++) {
                uint32_t bh[4], bl[4];
                int br = brow0 + ntp * 16;
                uint32_t bseg = ((uint32_t)(k16 * 2) + bhalf) ^ ((uint32_t)(br >> 1) & 3u);
                uint32_t bo = base + 16384 + (uint32_t)br * 64 + bseg * 16;
                LDSM4(bh, bo);
                LDSM4(bl, bo + 8192);
#pragma unroll
                for (int mt = 0; mt < 2; mt++) {
#pragma unroll
                    for (int h8 = 0; h8 < 2; h8++) {
                        float* cc = acc[mt][ntp * 2 + h8];
                        mma16816(cc, ah[mt], bh + h8 * 2);
                        mma16816(cc, ah[mt], bl + h8 * 2);
                        mma16816(cc, al[mt], bh + h8 * 2);
                    }
                }
            }
        }
    }

    float qs = (mode == 1 && z == 0) ? 0.125f : 1.0f;
#pragma unroll
    for (int mt = 0; mt < 2; mt++) {
#pragma unroll
        for (int nt8 = 0; nt8 < 8; nt8++) {
            const float* cc = acc[mt][nt8];
            int row = m0 + wm * 32 + mt * 16 + (lane >> 2);
            int col = n0 + wn * 64 + nt8 * 8 + (lane & 3) * 2;
            float bx = bias[col], by = bias[col + 1];
            float2 v0 = make_float2((cc[0] + bx) * qs, (cc[1] + by) * qs);
            float2 v1 = make_float2((cc[2] + bx) * qs, (cc[3] + by) * qs);
            if (mode == 1) {
                uint32_t* Ph = (z == 0) ? g_qh : (z == 1) ? g_kh : g_vh;
                uint32_t* Pl = (z == 0) ? g_ql : (z == 1) ? g_kl : g_vl;
                int h = col >> 6, d = col & 63;
                int bb = row >> 9, s = row & 511;
                size_t p0 = (((size_t)((bb * 16 + h) * 512 + s)) * 64 + d) >> 1;
                int bb2 = (row + 8) >> 9, s2 = (row + 8) & 511;
                size_t p1 = (((size_t)((bb2 * 16 + h) * 512 + s2)) * 64 + d) >> 1;
                uint32_t hi, lo;
                split2(v0.x, v0.y, hi, lo);
                Ph[p0] = hi; Pl[p0] = lo;
                split2(v1.x, v1.y, hi, lo);
                Ph[p1] = hi; Pl[p1] = lo;
            } else {
                *(float2*)&C0[(size_t)row * 1024 + col] = v0;
                *(float2*)&C0[(size_t)(row + 8) * 1024 + col] = v1;
            }
        }
    }
}

// ============ tensor-core flash attention with geometry bias ==================
static constexpr uint32_t ABUF = 36864;
static constexpr int ATTN_SMEM = 2 * 36864;   // 73728

__global__ __launch_bounds__(128) void attn_mma_kernel() {
    extern __shared__ __align__(16) char asmem[];
    uint32_t sbase = smem_u32(asmem);
    int tid = threadIdx.x, lane = tid & 31, w = tid >> 5;
    int q0 = blockIdx.x * 64, bh = blockIdx.y;
    size_t bhb = (size_t)bh * 65536;
    const char* pqh = (const char*)g_qh + bhb + (size_t)q0 * 128;
    const char* pql = (const char*)g_ql + bhb + (size_t)q0 * 128;
    const char* pkh = (const char*)g_kh + bhb;
    const char* pkl = (const char*)g_kl + bhb;
    const char* pvh = (const char*)g_vh + bhb;
    const char* pvl = (const char*)g_vl + bhb;
    const float* lbp = g_logb + (size_t)bh * 262144;

#pragma unroll
    for (int p = 0; p < 4; p++) {
        int id = tid + p * 128, row = id >> 3, seg = id & 7;
        uint32_t d = sbase + ABUF + (uint32_t)row * 144 + (uint32_t)seg * 16;
        int so = row * 128 + seg * 16;
        CP_ASYNC16(d, pqh + so);
        CP_ASYNC16(d + 9216, pql + so);
    }
    CP_COMMIT();
#pragma unroll
    for (int p = 0; p < 4; p++) {
        int id = tid + p * 128, row = id >> 3, seg = id & 7;
        uint32_t d = sbase + (uint32_t)row * 144 + (uint32_t)seg * 16;
        int so = row * 128 + seg * 16;
        CP_ASYNC16(d,         pkh + so);
        CP_ASYNC16(d + 9216,  pkl + so);
        CP_ASYNC16(d + 18432, pvh + so);
        CP_ASYNC16(d + 27648, pvl + so);
    }
    CP_COMMIT();
    CP_WAIT(1);
    __syncthreads();

    uint32_t qh[4][4], ql[4][4];
    {
        uint32_t aOff = (uint32_t)(w * 16 + (lane & 15)) * 144 + (uint32_t)(lane >> 4) * 16;
#pragma unroll
        for (int k16 = 0; k16 < 4; k16++) {
            LDSM4(qh[k16], sbase + ABUF + aOff + k16 * 32);
            LDSM4(ql[k16], sbase + ABUF + 9216 + aOff + k16 * 32);
        }
    }
    __syncthreads();

    float o[8][4];
#pragma unroll
    for (int t = 0; t < 8; t++)
#pragma unroll
        for (int q = 0; q < 4; q++) o[t][q] = 0.0f;
    float m0 = -1e30f, m1 = -1e30f, l0 = 0.0f, l1 = 0.0f;

    uint32_t bOffK = (uint32_t)((lane & 7) + ((lane >> 4) & 1) * 8) * 144
                   + (uint32_t)((lane >> 3) & 1) * 16;
    uint32_t vOff  = (uint32_t)((lane & 7) + ((lane >> 3) & 1) * 8) * 144
                   + (uint32_t)(lane >> 4) * 16;

    for (int c = 0; c < 8; c++) {
        if (c < 7) {
            int k0 = (c + 1) * 64;
            uint32_t bb = sbase + (uint32_t)((c + 1) & 1) * ABUF;
#pragma unroll
            for (int p = 0; p < 4; p++) {
                int id = tid + p * 128, row = id >> 3, seg = id & 7;
                uint32_t d = bb + (uint32_t)row * 144 + (uint32_t)seg * 16;
                int so = (k0 + row) * 128 + seg * 16;
                CP_ASYNC16(d,         pkh + so);
                CP_ASYNC16(d + 9216,  pkl + so);
                CP_ASYNC16(d + 18432, pvh + so);
                CP_ASYNC16(d + 27648, pvl + so);
            }
            CP_COMMIT();
            CP_WAIT(1);
        } else {
            CP_WAIT(0);
        }
        __syncthreads();
        uint32_t sb = sbase + (uint32_t)(c & 1) * ABUF;

        const float* lp = lbp + (size_t)(q0 + w * 16 + (lane >> 2)) * 512
                        + c * 64 + (lane & 3) * 2;
        float2 lbA[8], lbB[8];
#pragma unroll
        for (int t = 0; t < 8; t++) {
            lbA[t] = *(const float2*)(lp + t * 8);
            lbB[t] = *(const float2*)(lp + 4096 + t * 8);
        }

        float s[8][4];
#pragma unroll
        for (int t = 0; t < 8; t++)
#pragma unroll
            for (int q = 0; q < 4; q++) s[t][q] = 0.0f;
#pragma unroll
        for (int k16 = 0; k16 < 4; k16++) {
#pragma unroll
            for (int ntp = 0; ntp < 4; ntp++) {
                uint32_t bh4[4], bl4[4];
                uint32_t bo = sb + bOffK + (uint32_t)ntp * 2304 + (uint32_t)k16 * 32;
                LDSM4(bh4, bo);
                LDSM4(bl4, bo + 9216);
#pragma unroll
                for (int h8 = 0; h8 < 2; h8++) {
                    float* cc = s[ntp * 2 + h8];
                    mma16816(cc, qh[k16], bh4 + h8 * 2);
                    mma16816(cc, ql[k16], bh4 + h8 * 2);
                    mma16816(cc, qh[k16], bl4 + h8 * 2);
                }
            }
        }

        float rm0 = -1e30f, rm1 = -1e30f;
#pragma unroll
        for (int t = 0; t < 8; t++) {
            s[t][0] += lbA[t].x; s[t][1] += lbA[t].y;
            s[t][2] += lbB[t].x; s[t][3] += lbB[t].y;
            rm0 = fmaxf(rm0, fmaxf(s[t][0], s[t][1]));
            rm1 = fmaxf(rm1, fmaxf(s[t][2], s[t][3]));
        }
        rm0 = fmaxf(rm0, __shfl_xor_sync(0xffffffffu, rm0, 1, 4));
        rm0 = fmaxf(rm0, __shfl_xor_sync(0xffffffffu, rm0, 2, 4));
        rm1 = fmaxf(rm1, __shfl_xor_sync(0xffffffffu, rm1, 1, 4));
        rm1 = fmaxf(rm1, __shfl_xor_sync(0xffffffffu, rm1, 2, 4));
        float mn0 = fmaxf(m0, rm0), mn1 = fmaxf(m1, rm1);
        float c0 = __expf(m0 - mn0), c1 = __expf(m1 - mn1);
        m0 = mn0; m1 = mn1;
        float ps0 = 0.0f, ps1 = 0.0f;
#pragma unroll
        for (int t = 0; t < 8; t++) {
            s[t][0] = __expf(s[t][0] - mn0); ps0 += s[t][0];
            s[t][1] = __expf(s[t][1] - mn0); ps0 += s[t][1];
            s[t][2] = __expf(s[t][2] - mn1); ps1 += s[t][2];
            s[t][3] = __expf(s[t][3] - mn1); ps1 += s[t][3];
        }
        ps0 += __shfl_xor_sync(0xffffffffu, ps0, 1, 4);
        ps0 += __shfl_xor_sync(0xffffffffu, ps0, 2, 4);
        ps1 += __shfl_xor_sync(0xffffffffu, ps1, 1, 4);
        ps1 += __shfl_xor_sync(0xffffffffu, ps1, 2, 4);
        l0 = l0 * c0 + ps0; l1 = l1 * c1 + ps1;
#pragma unroll
        for (int t = 0; t < 8; t++) {
            o[t][0] *= c0; o[t][1] *= c0; o[t][2] *= c1; o[t][3] *= c1;
        }

        uint32_t ph[4][4], pl[4][4];
#pragma unroll
        for (int j = 0; j < 4; j++) {
            split2(s[2*j][0],   s[2*j][1],   ph[j][0], pl[j][0]);
            split2(s[2*j][2],   s[2*j][3],   ph[j][1], pl[j][1]);
            split2(s[2*j+1][0], s[2*j+1][1], ph[j][2], pl[j][2]);
            split2(s[2*j+1][2], s[2*j+1][3], ph[j][3], pl[j][3]);
        }

#pragma unroll
        for (int j = 0; j < 4; j++) {
#pragma unroll
            for (int np = 0; np < 4; np++) {
                uint32_t vh4[4], vl4[4];
                uint32_t vo = sb + 18432 + vOff + (uint32_t)j * 2304 + (uint32_t)np * 32;
                LDSM4T(vh4, vo);
                LDSM4T(vl4, vo + 9216);
#pragma unroll
                for (int h8 = 0; h8 < 2; h8++) {
                    float* cc = o[np * 2 + h8];
                    mma16816(cc, ph[j], vh4 + h8 * 2);
                    mma16816(cc, pl[j], vh4 + h8 * 2);
                    mma16816(cc, ph[j], vl4 + h8 * 2);
                }
            }
        }
        __syncthreads();
    }

    float i0 = 1.0f / l0, i1 = 1.0f / l1;
    int b = bh >> 4, hh = bh & 15;
    int r0 = q0 + w * 16 + (lane >> 2);
    size_t base0 = ((size_t)(b * 512 + r0) * 1024 + hh * 64 + (lane & 3) * 2) >> 1;
    size_t base1 = ((size_t)(b * 512 + r0 + 8) * 1024 + hh * 64 + (lane & 3) * 2) >> 1;
#pragma unroll
    for (int t = 0; t < 8; t++) {
        uint32_t hi, lo;
        split2(o[t][0] * i0, o[t][1] * i0, hi, lo);
        g_oh[base0 + t * 4] = hi; g_ol[base0 + t * 4] = lo;
        split2(o[t][2] * i1, o[t][3] * i1, hi, lo);
        g_oh[base1 + t * 4] = hi; g_ol[base1 + t * 4] = lo;
    }
}

// ---------------- launch ------------------------------------------------------
extern "C" void kernel_launch(void* const* d_in, const int* in_sizes, int n_in,
                              void* d_out, int out_size) {
    (void)in_sizes; (void)n_in; (void)out_size;
    const float* queries = (const float*)d_in[0];
    const float* keys    = (const float*)d_in[1];
    const float* values  = (const float*)d_in[2];
    const float* boxes   = (const float*)d_in[3];
    const float* bq = (const float*)d_in[5];
    const float* bk = (const float*)d_in[7];
    const float* bv = (const float*)d_in[9];
    const float* bo = (const float*)d_in[11];
    const float* Wq = (const float*)d_in[4];
    const float* Wk = (const float*)d_in[6];
    const float* Wv = (const float*)d_in[8];
    const float* Wo = (const float*)d_in[10];
    const float* Wg = (const float*)d_in[12];
    const float* bg = (const float*)d_in[13];
    float* out = (float*)d_out;

    cudaFuncSetAttribute(mma_gemm_kernel,
                         cudaFuncAttributeMaxDynamicSharedMemorySize, MG_SMEM);
    cudaFuncSetAttribute(attn_mma_kernel,
                         cudaFuncAttributeMaxDynamicSharedMemorySize, ATTN_SMEM);
    cudaFuncSetAttribute(bias_mma_kernel,
                         cudaFuncAttributeMaxDynamicSharedMemorySize, BIAS_SMEM);

    boxfeat_kernel<<<16, 256>>>(boxes);
    conv_all_kernel<<<16384, 256>>>(queries, keys, values, Wq, Wk, Wv, Wo);
    bias_mma_kernel<<<8192, 256, BIAS_SMEM>>>(Wg, bg);
    mma_gemm_kernel<<<dim3(32, 8, 3), 256, MG_SMEM>>>(
        bq, bk, bv, nullptr, /*a_sel=*/0, /*mode=*/1);
    attn_mma_kernel<<<dim3(8, 128), 128, ATTN_SMEM>>>();
    mma_gemm_kernel<<<dim3(32, 8, 1), 256, MG_SMEM>>>(
        bo, bo, bo, out, /*a_sel=*/1, /*mode=*/0);
}

// round 13
// speedup vs baseline: 2.6424x; 1.0195x over previous
#include <cuda_runtime.h>
#include <cuda_bf16.h>
#include <cuda_fp16.h>
#include <cstdint>

#define Bsz 8
#define Nsq 512
#define DM_ 1024
#define Hh 16
#define DK 64

// ---------------- scratch (static device arrays; no allocation) --------------
__device__ float g_logb[(size_t)Bsz*Hh*Nsq*Nsq]; // (b,h,n,m) fp32
__device__ float g_boxf[Bsz*Nsq*8];               // cx,cy,w,h,logw,logh
// packed bf16x2 hi/lo projections (b,h,n,d): idx = ((bh*512+n)*64+d)/2
__device__ uint32_t g_qh[Bsz*Hh*Nsq*DK/2];
__device__ uint32_t g_ql[Bsz*Hh*Nsq*DK/2];
__device__ uint32_t g_kh[Bsz*Hh*Nsq*DK/2];
__device__ uint32_t g_kl[Bsz*Hh*Nsq*DK/2];
__device__ uint32_t g_vh[Bsz*Hh*Nsq*DK/2];
__device__ uint32_t g_vl[Bsz*Hh*Nsq*DK/2];
// pre-converted GEMM operands (bf16 hi/lo pairs, row = 512 uint32)
__device__ uint32_t g_inh[3u*4096*512];   // queries/keys/values
__device__ uint32_t g_inl[3u*4096*512];
__device__ uint32_t g_wh[4u*1024*512];    // Wq,Wk,Wv,Wo
__device__ uint32_t g_wl[4u*1024*512];
__device__ uint32_t g_oh[4096u*512];      // attention output (b,n,h*64)
__device__ uint32_t g_ol[4096u*512];

// ---------------- helpers ----------------------------------------------------
__device__ __forceinline__ uint32_t smem_u32(const void* p) {
    uint32_t a;
    asm("{ .reg .u64 t; cvta.to.shared.u64 t, %1; cvt.u32.u64 %0, t; }" : "=r"(a) : "l"(p));
    return a;
}

#define LDSM4(r, a) \
    asm volatile("ldmatrix.sync.aligned.m8n8.x4.shared.b16 {%0,%1,%2,%3}, [%4];" \
        : "=r"((r)[0]), "=r"((r)[1]), "=r"((r)[2]), "=r"((r)[3]) : "r"(a))
#define LDSM4T(r, a) \
    asm volatile("ldmatrix.sync.aligned.m8n8.x4.trans.shared.b16 {%0,%1,%2,%3}, [%4];" \
        : "=r"((r)[0]), "=r"((r)[1]), "=r"((r)[2]), "=r"((r)[3]) : "r"(a))

#define CP_ASYNC16(dst, src) \
    asm volatile("cp.async.cg.shared.global [%0], [%1], 16;" :: "r"(dst), "l"(src) : "memory")
#define CP_COMMIT() asm volatile("cp.async.commit_group;" ::: "memory")
#define CP_WAIT(n)  asm volatile("cp.async.wait_group %0;" :: "n"(n) : "memory")

__device__ __forceinline__ void mma16816(float* c, const uint32_t* a, const uint32_t* b) {
    asm volatile("mma.sync.aligned.m16n8k16.row.col.f32.bf16.bf16.f32 "
        "{%0,%1,%2,%3}, {%4,%5,%6,%7}, {%8,%9}, {%0,%1,%2,%3};"
        : "+f"(c[0]), "+f"(c[1]), "+f"(c[2]), "+f"(c[3])
        : "r"(a[0]), "r"(a[1]), "r"(a[2]), "r"(a[3]), "r"(b[0]), "r"(b[1]));
}
__device__ __forceinline__ void mma16816h(float* c, const uint32_t* a, const uint32_t* b) {
    asm volatile("mma.sync.aligned.m16n8k16.row.col.f32.f16.f16.f32 "
        "{%0,%1,%2,%3}, {%4,%5,%6,%7}, {%8,%9}, {%0,%1,%2,%3};"
        : "+f"(c[0]), "+f"(c[1]), "+f"(c[2]), "+f"(c[3])
        : "r"(a[0]), "r"(a[1]), "r"(a[2]), "r"(a[3]), "r"(b[0]), "r"(b[1]));
}

// split two floats into packed bf16x2 hi + bf16x2 lo (residual)
__device__ __forceinline__ void split2(float x, float y, uint32_t& hi, uint32_t& lo) {
    asm("cvt.rn.bf16x2.f32 %0, %1, %2;" : "=r"(hi) : "f"(y), "f"(x));
    float fx = __uint_as_float(hi << 16);
    float fy = __uint_as_float(hi & 0xffff0000u);
    asm("cvt.rn.bf16x2.f32 %0, %1, %2;" : "=r"(lo) : "f"(y - fy), "f"(x - fx));
}
// fp16 variant
__device__ __forceinline__ void split2h(float x, float y, uint32_t& hi, uint32_t& lo) {
    __half2 h = __floats2half2_rn(x, y);
    hi = *reinterpret_cast<uint32_t*>(&h);
    float2 f = __half22float2(h);
    __half2 l = __floats2half2_rn(x - f.x, y - f.y);
    lo = *reinterpret_cast<uint32_t*>(&l);
}

// ---------------- box feature precompute ------------------------------------
__global__ void boxfeat_kernel(const float* __restrict__ boxes) {
    int i = blockIdx.x * 256 + threadIdx.x;            // < B*N = 4096
    float4 bx = *(const float4*)(boxes + (size_t)i * 4);
    float cx = (bx.x + bx.z) * 0.5f;
    float cy = (bx.y + bx.w) * 0.5f;
    float w  = (bx.z - bx.x) + 1.0f;
    float h  = (bx.w - bx.y) + 1.0f;
    float* o = g_boxf + (size_t)i * 8;
    o[0] = cx; o[1] = cy; o[2] = w; o[3] = h;
    o[4] = __logf(w); o[5] = __logf(h);
}

// ---------------- fused f32 -> bf16 hi/lo conversion (all 7 tensors) ----------
__global__ void conv_all_kernel(const float* __restrict__ q, const float* __restrict__ k,
                                const float* __restrict__ v, const float* __restrict__ wq,
                                const float* __restrict__ wk, const float* __restrict__ wv,
                                const float* __restrict__ wo) {
    size_t i = (size_t)blockIdx.x * 256 + threadIdx.x;   // < 4194304 float4s
    const float* src;
    uint32_t *dh, *dl;
    size_t off;
    if (i < 3145728) {
        int sel = (int)(i >> 20);
        off = i & 1048575;
        src = (sel == 0) ? q : (sel == 1) ? k : v;
        dh = g_inh + (size_t)sel * 2097152;
        dl = g_inl + (size_t)sel * 2097152;
    } else {
        size_t j = i - 3145728;
        int sel = (int)(j >> 18);
        off = j & 262143;
        src = (sel == 0) ? wq : (sel == 1) ? wk : (sel == 2) ? wv : wo;
        dh = g_wh + (size_t)sel * 524288;
        dl = g_wl + (size_t)sel * 524288;
    }
    float4 x = *(const float4*)(src + off * 4);
    uint32_t h0, l0, h1, l1;
    split2(x.x, x.y, h0, l0);
    split2(x.z, x.w, h1, l1);
    *(uint2*)(dh + off * 2) = make_uint2(h0, h1);
    *(uint2*)(dl + off * 2) = make_uint2(l0, l1);
}

// ============ device bodies: GEMM tile and bias block =========================
static constexpr int STAGE_B = 4 * 128 * 64;          // 32768
static constexpr int FUSED_SMEM = 3 * STAGE_B;        // 98304 (>= bias's 78336)

// ---- GEMM 128x128 tile body (3-stage cp.async ring, swizzled 64B rows) ------
__device__ __forceinline__ void gemm_tile_body(
        int bx, int by, int bz, char* smem,
        const float* b0p, const float* b1p, const float* b2p,
        float* C0, int a_sel, int mode) {
    int z = bz;
    const uint32_t* Ah;
    const uint32_t* Al;
    if (a_sel) { Ah = g_oh; Al = g_ol; }
    else       { Ah = g_inh + (size_t)z * 2097152; Al = g_inl + (size_t)z * 2097152; }
    int wsel = a_sel ? 3 : z;
    const uint32_t* Wh = g_wh + (size_t)wsel * 524288;
    const uint32_t* Wl = g_wl + (size_t)wsel * 524288;
    const float* bias = (z == 0) ? b0p : (z == 1) ? b1p : b2p;

    uint32_t sbase = smem_u32(smem);
    int tid = threadIdx.x;
    int lane = tid & 31, wid = tid >> 5;
    int wm = wid & 3, wn = wid >> 2;
    int m0 = bx * 128, n0 = by * 128;

    const uint32_t* srcb[4];
    srcb[0] = Ah + (size_t)m0 * 512;
    srcb[1] = Al + (size_t)m0 * 512;
    srcb[2] = Wh + (size_t)n0 * 512;
    srcb[3] = Wl + (size_t)n0 * 512;

    int arow0 = wm * 32 + (lane & 15);
    uint32_t ahalf = (uint32_t)(lane >> 4);
    int brow0 = wn * 64 + (lane & 7) + ((lane >> 4) & 1) * 8;
    uint32_t bhalf = (uint32_t)((lane >> 3) & 1);

    float acc[2][8][4];
#pragma unroll
    for (int i = 0; i < 2; i++)
#pragma unroll
        for (int j = 0; j < 8; j++)
#pragma unroll
            for (int q = 0; q < 4; q++) acc[i][j][q] = 0.0f;

    // prologue: chunks 0 and 1
#pragma unroll
    for (int pc = 0; pc < 2; pc++) {
        uint32_t bb = sbase + (uint32_t)pc * STAGE_B;
        int k0 = pc * 16;
#pragma unroll
        for (int p = 0; p < 8; p++) {
            int mat = p >> 1;
            int id2 = tid + (p & 1) * 256;
            int row = id2 >> 2, seg = id2 & 3;
            uint32_t dst = bb + (uint32_t)mat * 8192 + (uint32_t)row * 64
                         + (uint32_t)((seg ^ ((row >> 1) & 3)) * 16);
            CP_ASYNC16(dst, srcb[mat] + (size_t)row * 512 + k0 + seg * 4);
        }
        CP_COMMIT();
    }

    for (int c = 0; c < 32; ++c) {
        if (c < 31) { CP_WAIT(1); } else { CP_WAIT(0); }
        __syncthreads();

        if (c + 2 < 32) {
            uint32_t bb = sbase + (uint32_t)((c + 2) % 3) * STAGE_B;
            int k0 = (c + 2) * 16;
#pragma unroll
            for (int p = 0; p < 8; p++) {
                int mat = p >> 1;
                int id2 = tid + (p & 1) * 256;
                int row = id2 >> 2, seg = id2 & 3;
                uint32_t dst = bb + (uint32_t)mat * 8192 + (uint32_t)row * 64
                             + (uint32_t)((seg ^ ((row >> 1) & 3)) * 16);
                CP_ASYNC16(dst, srcb[mat] + (size_t)row * 512 + k0 + seg * 4);
            }
            CP_COMMIT();
        }

        uint32_t base = sbase + (uint32_t)(c % 3) * STAGE_B;
#pragma unroll
        for (int k16 = 0; k16 < 2; k16++) {
            uint32_t ah[2][4], al[2][4];
#pragma unroll
            for (int mt = 0; mt < 2; mt++) {
                int ar = arow0 + mt * 16;
                uint32_t aseg = ((uint32_t)(k16 * 2) + ahalf) ^ ((uint32_t)(ar >> 1) & 3u);
                uint32_t ao = base + (uint32_t)ar * 64 + aseg * 16;
                LDSM4(ah[mt], ao);
                LDSM4(al[mt], ao + 8192);
            }
#pragma unroll
            for (int ntp = 0; ntp < 4; ntp++) {
                uint32_t bh[4], bl[4];
                int br = brow0 + ntp * 16;
                uint32_t bseg = ((uint32_t)(k16 * 2) + bhalf) ^ ((uint32_t)(br >> 1) & 3u);
                uint32_t bo = base + 16384 + (uint32_t)br * 64 + bseg * 16;
                LDSM4(bh, bo);
                LDSM4(bl, bo + 8192);
#pragma unroll
                for (int mt = 0; mt < 2; mt++) {
#pragma unroll
                    for (int h8 = 0; h8 < 2; h8++) {
                        float* cc = acc[mt][ntp * 2 + h8];
                        mma16816(cc, ah[mt], bh + h8 * 2);
                        mma16816(cc, ah[mt], bl + h8 * 2);
                        mma16816(cc, al[mt], bh + h8 * 2);
                    }
                }
            }
        }
    }

    float qs = (mode == 1 && z == 0) ? 0.125f : 1.0f;
#pragma unroll
    for (int mt = 0; mt < 2; mt++) {
#pragma unroll
        for (int nt8 = 0; nt8 < 8; nt8++) {
            const float* cc = acc[mt][nt8];
            int row = m0 + wm * 32 + mt * 16 + (lane >> 2);
            int col = n0 + wn * 64 + nt8 * 8 + (lane & 3) * 2;
            float bx2 = bias[col], by2 = bias[col + 1];
            float2 v0 = make_float2((cc[0] + bx2) * qs, (cc[1] + by2) * qs);
            float2 v1 = make_float2((cc[2] + bx2) * qs, (cc[3] + by2) * qs);
            if (mode == 1) {
                uint32_t* Ph = (z == 0) ? g_qh : (z == 1) ? g_kh : g_vh;
                uint32_t* Pl = (z == 0) ? g_ql : (z == 1) ? g_kl : g_vl;
                int h = col >> 6, d = col & 63;
                int bb = row >> 9, s = row & 511;
                size_t p0 = (((size_t)((bb * 16 + h) * 512 + s)) * 64 + d) >> 1;
                int bb2 = (row + 8) >> 9, s2 = (row + 8) & 511;
                size_t p1 = (((size_t)((bb2 * 16 + h) * 512 + s2)) * 64 + d) >> 1;
                uint32_t hi, lo;
                split2(v0.x, v0.y, hi, lo);
                Ph[p0] = hi; Pl[p0] = lo;
                split2(v1.x, v1.y, hi, lo);
                Ph[p1] = hi; Pl[p1] = lo;
            } else {
                *(float2*)&C0[(size_t)row * 1024 + col] = v0;
                *(float2*)&C0[(size_t)(row + 8) * 1024 + col] = v1;
            }
        }
    }
}

// ---- bias block body (fp16x2 HMMA + coalesced smem-transposed stores) --------
__device__ __forceinline__ void bias_block_body(
        int blk, char* bsm, const float* Wg, const float* bg) {
    __shared__ float bgs[16];
    uint32_t sb = smem_u32(bsm);
    int tid = threadIdx.x, lane = tid & 31, w = tid >> 5;
    int m0 = (blk & 1) * 256;
    int n  = (blk >> 1) & 511;
    int b  = blk >> 10;
    int m  = m0 + tid;

    if (tid < 16) bgs[tid] = bg[tid];
    {
        int row = tid >> 4, k4 = (tid & 15) * 4;
        float4 wv4 = *(const float4*)(Wg + row * 64 + k4);
        uint32_t h0, l0, h1, l1;
        split2h(wv4.x, wv4.y, h0, l0);
        split2h(wv4.z, wv4.w, h1, l1);
        *(uint2*)(bsm + 73728 + row * 144 + k4 * 2) = make_uint2(h0, h1);
        *(uint2*)(bsm + 76032 + row * 144 + k4 * 2) = make_uint2(l0, l1);
    }

    const float* fn = g_boxf + (size_t)(b * 512 + n) * 8;
    const float* fm = g_boxf + (size_t)(b * 512 + m) * 8;
    float pos[4];
    pos[0] = __logf(fmaxf(fabsf(fn[0] - fm[0]) / fn[2], 1e-3f)) * 100.0f;
    pos[1] = __logf(fmaxf(fabsf(fn[1] - fm[1]) / fn[3], 1e-3f)) * 100.0f;
    pos[2] = (fn[4] - fm[4]) * 100.0f;
    pos[3] = (fn[5] - fm[5]) * 100.0f;

    const float DMAT[8] = {1.0f, 0.4216965034f, 0.1778279410f, 0.0749894209f,
                           0.0316227766f, 0.0133352143f, 0.0056234133f, 0.0023713737f};

#pragma unroll
    for (int d = 0; d < 4; d++) {
        float sv[8], cv[8];
#pragma unroll
        for (int j = 0; j < 8; j++) __sincosf(pos[d] * DMAT[j], &sv[j], &cv[j]);
        uint32_t sh[4], sl[4], ch[4], cl[4];
#pragma unroll
        for (int p = 0; p < 4; p++) {
            split2h(sv[2*p], sv[2*p+1], sh[p], sl[p]);
            split2h(cv[2*p], cv[2*p+1], ch[p], cl[p]);
        }
        *(uint4*)(bsm + tid * 144 + d * 16)          = make_uint4(sh[0], sh[1], sh[2], sh[3]);
        *(uint4*)(bsm + 36864 + tid * 144 + d * 16)  = make_uint4(sl[0], sl[1], sl[2], sl[3]);
        *(uint4*)(bsm + tid * 144 + (4 + d) * 16)         = make_uint4(ch[0], ch[1], ch[2], ch[3]);
        *(uint4*)(bsm + 36864 + tid * 144 + (4 + d) * 16) = make_uint4(cl[0], cl[1], cl[2], cl[3]);
    }
    __syncthreads();

    uint32_t aOff = sb + (uint32_t)(w * 32 + (lane & 15)) * 144 + (uint32_t)(lane >> 4) * 16;
    uint32_t bOff = sb + 73728 + (uint32_t)((lane & 7) + ((lane >> 4) & 1) * 8) * 144
                  + (uint32_t)((lane >> 3) & 1) * 16;
    float acc[2][2][4];
#pragma unroll
    for (int mt = 0; mt < 2; mt++)
#pragma unroll
        for (int n8 = 0; n8 < 2; n8++)
#pragma unroll
            for (int qq = 0; qq < 4; qq++) acc[mt][n8][qq] = 0.0f;

#pragma unroll
    for (int k16 = 0; k16 < 4; k16++) {
        uint32_t bh4[4], bl4[4];
        LDSM4(bh4, bOff + k16 * 32);
        LDSM4(bl4, bOff + 2304 + k16 * 32);
#pragma unroll
        for (int mt = 0; mt < 2; mt++) {
            uint32_t ah[4], al[4];
            LDSM4(ah, aOff + (uint32_t)mt * (16 * 144) + k16 * 32);
            LDSM4(al, aOff + 36864 + (uint32_t)mt * (16 * 144) + k16 * 32);
#pragma unroll
            for (int n8 = 0; n8 < 2; n8++) {
                float* cc = acc[mt][n8];
                mma16816h(cc, ah, bh4 + n8 * 2);
                mma16816h(cc, ah, bl4 + n8 * 2);
                mma16816h(cc, al, bh4 + n8 * 2);
            }
        }
    }

    // transpose through smem (pitch 260 floats -> conflict-free), then
    // coalesced 1KB-per-head global stores
    __syncthreads();
    float* tr = (float*)bsm;     // 16 heads x 260-float pitch = 16640 B
#pragma unroll
    for (int mt = 0; mt < 2; mt++) {
#pragma unroll
        for (int n8 = 0; n8 < 2; n8++) {
#pragma unroll
            for (int r2 = 0; r2 < 2; r2++) {
#pragma unroll
                for (int j = 0; j < 2; j++) {
                    int row = w * 32 + mt * 16 + (lane >> 2) + r2 * 8;
                    int col = n8 * 8 + (lane & 3) * 2 + j;
                    float g = acc[mt][n8][r2 * 2 + j] + bgs[col];
                    tr[col * 260 + row] = __logf(fmaxf(g, 1e-6f));
                }
            }
        }
    }
    __syncthreads();
    {
        int h = tid >> 4, mseg = (tid & 15) * 16;
        size_t gb = ((size_t)(b * 16 + h)) * 262144 + (size_t)n * 512 + m0 + mseg;
        const float* src = tr + h * 260 + mseg;
#pragma unroll
        for (int q = 0; q < 4; q++)
            *(float4*)&g_logb[gb + q * 4] = *(const float4*)(src + q * 4);
    }
}

// ---- fused launch: blocks [0,768) = QKV GEMM tiles, [768,8960) = bias --------
__global__ __launch_bounds__(256, 2) void fused_gemm_bias_kernel(
        const float* __restrict__ b0p, const float* __restrict__ b1p,
        const float* __restrict__ b2p, float* __restrict__ C0,
        const float* __restrict__ Wg, const float* __restrict__ bg,
        int a_sel, int mode) {
    extern __shared__ char smem[];
    int id = blockIdx.x;
    if (id < 768) {
        int z = id >> 8, rem = id & 255;
        gemm_tile_body(rem & 31, rem >> 5, z, smem, b0p, b1p, b2p, C0, a_sel, mode);
    } else {
        bias_block_body(id - 768, smem, Wg, bg);
    }
}

// ============ tensor-core flash attention with geometry bias ==================
static constexpr uint32_t ABUF = 36864;
static constexpr int ATTN_SMEM = 2 * 36864;   // 73728

__global__ __launch_bounds__(128) void attn_mma_kernel() {
    extern __shared__ __align__(16) char asmem[];
    uint32_t sbase = smem_u32(asmem);
    int tid = threadIdx.x, lane = tid & 31, w = tid >> 5;
    int q0 = blockIdx.x * 64, bh = blockIdx.y;
    size_t bhb = (size_t)bh * 65536;
    const char* pqh = (const char*)g_qh + bhb + (size_t)q0 * 128;
    const char* pql = (const char*)g_ql + bhb + (size_t)q0 * 128;
    const char* pkh = (const char*)g_kh + bhb;
    const char* pkl = (const char*)g_kl + bhb;
    const char* pvh = (const char*)g_vh + bhb;
    const char* pvl = (const char*)g_vl + bhb;
    const float* lbp = g_logb + (size_t)bh * 262144;

#pragma unroll
    for (int p = 0; p < 4; p++) {
        int id = tid + p * 128, row = id >> 3, seg = id & 7;
        uint32_t d = sbase + ABUF + (uint32_t)row * 144 + (uint32_t)seg * 16;
        int so = row * 128 + seg * 16;
        CP_ASYNC16(d, pqh + so);
        CP_ASYNC16(d + 9216, pql + so);
    }
    CP_COMMIT();
#pragma unroll
    for (int p = 0; p < 4; p++) {
        int id = tid + p * 128, row = id >> 3, seg = id & 7;
        uint32_t d = sbase + (uint32_t)row * 144 + (uint32_t)seg * 16;
        int so = row * 128 + seg * 16;
        CP_ASYNC16(d,         pkh + so);
        CP_ASYNC16(d + 9216,  pkl + so);
        CP_ASYNC16(d + 18432, pvh + so);
        CP_ASYNC16(d + 27648, pvl + so);
    }
    CP_COMMIT();
    CP_WAIT(1);
    __syncthreads();

    uint32_t qh[4][4], ql[4][4];
    {
        uint32_t aOff = (uint32_t)(w * 16 + (lane & 15)) * 144 + (uint32_t)(lane >> 4) * 16;
#pragma unroll
        for (int k16 = 0; k16 < 4; k16++) {
            LDSM4(qh[k16], sbase + ABUF + aOff + k16 * 32);
            LDSM4(ql[k16], sbase + ABUF + 9216 + aOff + k16 * 32);
        }
    }
    __syncthreads();

    float o[8][4];
#pragma unroll
    for (int t = 0; t < 8; t++)
#pragma unroll
        for (int q = 0; q < 4; q++) o[t][q] = 0.0f;
    float m0 = -1e30f, m1 = -1e30f, l0 = 0.0f, l1 = 0.0f;

    uint32_t bOffK = (uint32_t)((lane & 7) + ((lane >> 4) & 1) * 8) * 144
                   + (uint32_t)((lane >> 3) & 1) * 16;
    uint32_t vOff  = (uint32_t)((lane & 7) + ((lane >> 3) & 1) * 8) * 144
                   + (uint32_t)(lane >> 4) * 16;

    for (int c = 0; c < 8; c++) {
        if (c < 7) {
            int k0 = (c + 1) * 64;
            uint32_t bb = sbase + (uint32_t)((c + 1) & 1) * ABUF;
#pragma unroll
            for (int p = 0; p < 4; p++) {
                int id = tid + p * 128, row = id >> 3, seg = id & 7;
                uint32_t d = bb + (uint32_t)row * 144 + (uint32_t)seg * 16;
                int so = (k0 + row) * 128 + seg * 16;
                CP_ASYNC16(d,         pkh + so);
                CP_ASYNC16(d + 9216,  pkl + so);
                CP_ASYNC16(d + 18432, pvh + so);
                CP_ASYNC16(d + 27648, pvl + so);
            }
            CP_COMMIT();
            CP_WAIT(1);
        } else {
            CP_WAIT(0);
        }
        __syncthreads();
        uint32_t sb = sbase + (uint32_t)(c & 1) * ABUF;

        const float* lp = lbp + (size_t)(q0 + w * 16 + (lane >> 2)) * 512
                        + c * 64 + (lane & 3) * 2;
        float2 lbA[8], lbB[8];
#pragma unroll
        for (int t = 0; t < 8; t++) {
            lbA[t] = *(const float2*)(lp + t * 8);
            lbB[t] = *(const float2*)(lp + 4096 + t * 8);
        }

        float s[8][4];
#pragma unroll
        for (int t = 0; t < 8; t++)
#pragma unroll
            for (int q = 0; q < 4; q++) s[t][q] = 0.0f;
#pragma unroll
        for (int k16 = 0; k16 < 4; k16++) {
#pragma unroll
            for (int ntp = 0; ntp < 4; ntp++) {
                uint32_t bh4[4], bl4[4];
                uint32_t bo = sb + bOffK + (uint32_t)ntp * 2304 + (uint32_t)k16 * 32;
                LDSM4(bh4, bo);
                LDSM4(bl4, bo + 9216);
#pragma unroll
                for (int h8 = 0; h8 < 2; h8++) {
                    float* cc = s[ntp * 2 + h8];
                    mma16816(cc, qh[k16], bh4 + h8 * 2);
                    mma16816(cc, ql[k16], bh4 + h8 * 2);
                    mma16816(cc, qh[k16], bl4 + h8 * 2);
                }
            }
        }

        float rm0 = -1e30f, rm1 = -1e30f;
#pragma unroll
        for (int t = 0; t < 8; t++) {
            s[t][0] += lbA[t].x; s[t][1] += lbA[t].y;
            s[t][2] += lbB[t].x; s[t][3] += lbB[t].y;
            rm0 = fmaxf(rm0, fmaxf(s[t][0], s[t][1]));
            rm1 = fmaxf(rm1, fmaxf(s[t][2], s[t][3]));
        }
        rm0 = fmaxf(rm0, __shfl_xor_sync(0xffffffffu, rm0, 1, 4));
        rm0 = fmaxf(rm0, __shfl_xor_sync(0xffffffffu, rm0, 2, 4));
        rm1 = fmaxf(rm1, __shfl_xor_sync(0xffffffffu, rm1, 1, 4));
        rm1 = fmaxf(rm1, __shfl_xor_sync(0xffffffffu, rm1, 2, 4));
        float mn0 = fmaxf(m0, rm0), mn1 = fmaxf(m1, rm1);
        float c0 = __expf(m0 - mn0), c1 = __expf(m1 - mn1);
        m0 = mn0; m1 = mn1;
        float ps0 = 0.0f, ps1 = 0.0f;
#pragma unroll
        for (int t = 0; t < 8; t++) {
            s[t][0] = __expf(s[t][0] - mn0); ps0 += s[t][0];
            s[t][1] = __expf(s[t][1] - mn0); ps0 += s[t][1];
            s[t][2] = __expf(s[t][2] - mn1); ps1 += s[t][2];
            s[t][3] = __expf(s[t][3] - mn1); ps1 += s[t][3];
        }
        ps0 += __shfl_xor_sync(0xffffffffu, ps0, 1, 4);
        ps0 += __shfl_xor_sync(0xffffffffu, ps0, 2, 4);
        ps1 += __shfl_xor_sync(0xffffffffu, ps1, 1, 4);
        ps1 += __shfl_xor_sync(0xffffffffu, ps1, 2, 4);
        l0 = l0 * c0 + ps0; l1 = l1 * c1 + ps1;
#pragma unroll
        for (int t = 0; t < 8; t++) {
            o[t][0] *= c0; o[t][1] *= c0; o[t][2] *= c1; o[t][3] *= c1;
        }

        uint32_t ph[4][4], pl[4][4];
#pragma unroll
        for (int j = 0; j < 4; j++) {
            split2(s[2*j][0],   s[2*j][1],   ph[j][0], pl[j][0]);
            split2(s[2*j][2],   s[2*j][3],   ph[j][1], pl[j][1]);
            split2(s[2*j+1][0], s[2*j+1][1], ph[j][2], pl[j][2]);
            split2(s[2*j+1][2], s[2*j+1][3], ph[j][3], pl[j][3]);
        }

#pragma unroll
        for (int j = 0; j < 4; j++) {
#pragma unroll
            for (int np = 0; np < 4; np++) {
                uint32_t vh4[4], vl4[4];
                uint32_t vo = sb + 18432 + vOff + (uint32_t)j * 2304 + (uint32_t)np * 32;
                LDSM4T(vh4, vo);
                LDSM4T(vl4, vo + 9216);
#pragma unroll
                for (int h8 = 0; h8 < 2; h8++) {
                    float* cc = o[np * 2 + h8];
                    mma16816(cc, ph[j], vh4 + h8 * 2);
                    mma16816(cc, pl[j], vh4 + h8 * 2);
                    mma16816(cc, ph[j], vl4 + h8 * 2);
                }
            }
        }
        __syncthreads();
    }

    float i0 = 1.0f / l0, i1 = 1.0f / l1;
    int b = bh >> 4, hh = bh & 15;
    int r0 = q0 + w * 16 + (lane >> 2);
    size_t base0 = ((size_t)(b * 512 + r0) * 1024 + hh * 64 + (lane & 3) * 2) >> 1;
    size_t base1 = ((size_t)(b * 512 + r0 + 8) * 1024 + hh * 64 + (lane & 3) * 2) >> 1;
#pragma unroll
    for (int t = 0; t < 8; t++) {
        uint32_t hi, lo;
        split2(o[t][0] * i0, o[t][1] * i0, hi, lo);
        g_oh[base0 + t * 4] = hi; g_ol[base0 + t * 4] = lo;
        split2(o[t][2] * i1, o[t][3] * i1, hi, lo);
        g_oh[base1 + t * 4] = hi; g_ol[base1 + t * 4] = lo;
    }
}

// ---------------- launch ------------------------------------------------------
extern "C" void kernel_launch(void* const* d_in, const int* in_sizes, int n_in,
                              void* d_out, int out_size) {
    (void)in_sizes; (void)n_in; (void)out_size;
    const float* queries = (const float*)d_in[0];
    const float* keys    = (const float*)d_in[1];
    const float* values  = (const float*)d_in[2];
    const float* boxes   = (const float*)d_in[3];
    const float* bq = (const float*)d_in[5];
    const float* bk = (const float*)d_in[7];
    const float* bv = (const float*)d_in[9];
    const float* bo = (const float*)d_in[11];
    const float* Wq = (const float*)d_in[4];
    const float* Wk = (const float*)d_in[6];
    const float* Wv = (const float*)d_in[8];
    const float* Wo = (const float*)d_in[10];
    const float* Wg = (const float*)d_in[12];
    const float* bg = (const float*)d_in[13];
    float* out = (float*)d_out;

    cudaFuncSetAttribute(fused_gemm_bias_kernel,
                         cudaFuncAttributeMaxDynamicSharedMemorySize, FUSED_SMEM);
    cudaFuncSetAttribute(attn_mma_kernel,
                         cudaFuncAttributeMaxDynamicSharedMemorySize, ATTN_SMEM);

    boxfeat_kernel<<<16, 256>>>(boxes);
    conv_all_kernel<<<16384, 256>>>(queries, keys, values, Wq, Wk, Wv, Wo);
    // QKV projections (768 tiles) + geometry bias (8192 blocks) in ONE launch
    fused_gemm_bias_kernel<<<8960, 256, FUSED_SMEM>>>(
        bq, bk, bv, nullptr, Wg, bg, /*a_sel=*/0, /*mode=*/1);
    attn_mma_kernel<<<dim3(8, 128), 128, ATTN_SMEM>>>();
    // output projection (GEMM-only blocks)
    fused_gemm_bias_kernel<<<256, 256, FUSED_SMEM>>>(
        bo, bo, bo, out, Wg, bg, /*a_sel=*/1, /*mode=*/0);
}